// round 7
// baseline (speedup 1.0000x reference)
#include <cuda_runtime.h>

// ------- scratch: 3 x 64MB = 192MB; referenced ONLY from device code ------
static __device__ float bA[16777216];
static __device__ float bB[16777216];
static __device__ float bP[16777216];   // p0|p1 (stage D), then p0b|p1b (stage E)

__device__ __forceinline__ float* gbuf(int t) {
    return t == 0 ? bA : (t == 1 ? bB : bP);
}

// ---------------- filters ------------------------------------------------
__constant__ float c_h[9] = {
     0.037828455506995f, -0.02384946501938f, -0.11062440441842f,
     0.37740285561265f,   0.8526986790094f,   0.37740285561265f,
    -0.11062440441842f,  -0.02384946501938f,  0.037828455506995f };
__constant__ float c_g[7] = {
    -0.064538882628938f, -0.040689417609558f, 0.41809227322221f,
     0.78848561640566f,   0.41809227322221f, -0.040689417609558f,
    -0.064538882628938f };
__constant__ float c_f[12] = {
     0.0144f,  0.0272f,  0.0526f,  0.0972f,  0.193f,  0.63f,
    -0.63f,   -0.193f,  -0.0972f, -0.0526f, -0.0272f, -0.0144f };

#define INV_SQ2 0.7071067811865476f
#define SQ2     1.4142135623730951f
#define SEG     4194304L
#define HM 8388608
#define FM 16777216

// --- Stage A/B (validated by output 0) -----------------------------------
__global__ void __launch_bounds__(256) k_vh(const float* __restrict__ x) {
    int idx = blockIdx.x * 256 + threadIdx.x;
    if (idx >= HM) return;
    int j = idx & 255, i2 = (idx >> 8) & 127, img = idx >> 15;
    const float* xi = x + ((long)img << 16);
    float s = 0.f;
#pragma unroll
    for (int k = 0; k < 9; ++k)
        s = fmaf(c_h[k], xi[(((2 * i2 + k - 4) & 255) << 8) + j], s);
    bA[idx] = s;
}
__global__ void __launch_bounds__(256) k_hh(float* __restrict__ outc) {
    int idx = blockIdx.x * 256 + threadIdx.x;
    if (idx >= 4194304) return;
    int j = idx & 127, i = (idx >> 7) & 127, img = idx >> 14;
    const float* t = bA + ((long)img << 15) + (i << 8);
    float s = 0.f;
#pragma unroll
    for (int k = 0; k < 9; ++k)
        s = fmaf(c_h[k], t[(2 * j + k - 4) & 255], s);
    outc[idx] = s;
}

// --- generic periodic conv over scratch buffers (tags, not pointers) ------
__global__ void __launch_bounds__(256) conv_per(
    int srcTag, long srcOff, int dstTag, long dstOff,
    int sW, int sH, int taps, int off, int fid, int vert, int total) {
    int idx = blockIdx.x * 256 + threadIdx.x;
    if (idx >= total) return;
    const float* src = gbuf(srcTag) + srcOff;
    float* dst = gbuf(dstTag) + dstOff;
    int Wm = (1 << sW) - 1, Hm = (1 << sH) - 1;
    int j = idx & Wm, i = (idx >> sW) & Hm;
    long base = (long)(idx >> (sW + sH)) << (sW + sH);
    const float* F = fid ? c_f : c_g;
    float a = 0.f;
    for (int k = 0; k < taps; ++k) {
        int ii = i, jj = j;
        if (vert) ii = (i + k - off) & Hm; else jj = (j + k - off) & Wm;
        a = fmaf(F[k], src[base + ((long)ii << sW) + jj], a);
    }
    dst[idx] = a;
}

// --- Stage C (literal) ----------------------------------------------------
// up = zeros; up[::2,::2] = c  (c read from out seg0) -> bA
__global__ void __launch_bounds__(256) k_up(const float* __restrict__ cc) {
    int idx = blockIdx.x * 256 + threadIdx.x;
    if (idx >= FM) return;
    int j = idx & 255, i = (idx >> 8) & 255, img = idx >> 16;
    float v = 0.f;
    if (((i | j) & 1) == 0)
        v = cc[((long)img << 14) + ((i >> 1) << 7) + (j >> 1)];
    bA[idx] = v;
}
// d = x - bA -> bB
__global__ void __launch_bounds__(256) k_sub(const float* __restrict__ x) {
    int idx = blockIdx.x * 256 + threadIdx.x;
    if (idx >= FM) return;
    bB[idx] = x[idx] - bA[idx];
}

// --- Stage D gathers ------------------------------------------------------
// y = resamp(d,2): bA[i,j] = bB[(i-j)%256, j]
__global__ void __launch_bounds__(256) k_resamp2() {
    int idx = blockIdx.x * 256 + threadIdx.x;
    if (idx >= FM) return;
    int j = idx & 255, i = (idx >> 8) & 255, img = idx >> 16;
    bA[idx] = bB[((long)img << 16) + (((i - j) & 255) << 8) + j];
}
// ye[i,j]=y[2i,j] -> bB[0..); p1pre[i,j]=y[2i+1,(j+1)%256] -> bB[HM..)
__global__ void __launch_bounds__(256) k_pp1() {
    int idx = blockIdx.x * 256 + threadIdx.x;
    if (idx >= HM) return;
    int j = idx & 255, i = (idx >> 8) & 127, img = idx >> 15;
    const float* yi = bA + ((long)img << 16);
    bB[idx]      = yi[((2 * i) << 8) + j];
    bB[HM + idx] = yi[((2 * i + 1) << 8) + ((j + 1) & 255)];
}
// resamp t=3 on (128,256): bP[dstOff+..][i,j] = bB[srcOff+..][i,(i+j)%256]
__global__ void __launch_bounds__(256) k_resamp3(long srcOff, long dstOff) {
    int idx = blockIdx.x * 256 + threadIdx.x;
    if (idx >= HM) return;
    int j = idx & 255, i = (idx >> 8) & 127, img = idx >> 15;
    bP[dstOff + idx] = bB[srcOff + ((long)img << 15) + (i << 8) + ((i + j) & 255)];
}

// --- qper_col vertical 12-tap f on (128,256), dst = bA --------------------
// srcTag >= 0: scratch buffer; srcTag < 0: ext pointer (e.g. z in out buf)
__global__ void __launch_bounds__(256) k_vq(const float* __restrict__ ext,
                                            int srcTag, long srcOff, int off) {
    int idx = blockIdx.x * 256 + threadIdx.x;
    if (idx >= HM) return;
    int j = idx & 255, i = (idx >> 8) & 127, img = idx >> 15;
    const float* base = (srcTag < 0) ? ext : (gbuf(srcTag) + srcOff);
    const float* s = base + ((long)img << 15);
    float a = 0.f;
#pragma unroll
    for (int k = 0; k < 12; ++k) {
        int r = i + k - off, sh = 0;
        if (r < 0)        { r += 128; sh = 128; }
        else if (r > 127) { r -= 128; sh = 128; }
        a = fmaf(c_f[k], s[(r << 8) + ((j + sh) & 255)], a);
    }
    bA[idx] = a;
}

// --- ladder combines ------------------------------------------------------
// y0 = (p0 - s)*inv_sq2; p0 = bP[0..), s = bB
__global__ void __launch_bounds__(256) k_y0c(float* __restrict__ y0) {
    int idx = blockIdx.x * 256 + threadIdx.x;
    if (idx >= HM) return;
    y0[idx] = (bP[idx] - bB[idx]) * INV_SQ2;
}
// y1 = -sq2*p1 - s; p1 = bP[HM..), s = bB
__global__ void __launch_bounds__(256) k_y1c(float* __restrict__ y1) {
    int idx = blockIdx.x * 256 + threadIdx.x;
    if (idx >= HM) return;
    y1[idx] = -SQ2 * bP[HM + idx] - bB[idx];
}

// --- Stage E gathers ------------------------------------------------------
// y4 = resamp(z,4): bA[i,j] = z[i,(j-i)%256]; z halves at zp / zp+HM
__global__ void __launch_bounds__(256) k_resamp4(const float* __restrict__ zp) {
    int idx = blockIdx.x * 256 + threadIdx.x;
    if (idx >= FM) return;
    int j = idx & 255, i = (idx >> 8) & 127, img = idx >> 15;   // img in [0,512)
    int b = img >> 7, ch = img & 127;
    const float* zi = (ch < 64)
        ? (zp      + ((long)((b << 6) + ch)      << 15))
        : (zp + HM + ((long)((b << 6) + ch - 64) << 15));
    bA[idx] = zi[(i << 8) + ((j - i) & 255)];
}
// pp0[i,j]=y4[i,2j] -> bB[0..); pp1[i,j]=y4[(i+1)%128,2j+1] -> bB[HM..)
__global__ void __launch_bounds__(256) k_pp2() {
    int idx = blockIdx.x * 256 + threadIdx.x;
    if (idx >= HM) return;
    int j = idx & 127, i = (idx >> 7) & 127, img = idx >> 14;
    const float* yi = bA + ((long)img << 15);
    bB[idx]      = yi[(i << 8) + 2 * j];
    bB[HM + idx] = yi[(((i + 1) & 127) << 8) + 2 * j + 1];
}
// resamp t=1 on (128,128): bP[dstOff..][i,j] = bB[srcOff..][(i+j)%128, j]
__global__ void __launch_bounds__(256) k_resamp1(long srcOff, long dstOff) {
    int idx = blockIdx.x * 256 + threadIdx.x;
    if (idx >= HM) return;
    int j = idx & 127, i = (idx >> 7) & 127, img = idx >> 14;
    bP[dstOff + idx] = bB[srcOff + ((long)img << 14) + (((i + j) & 127) << 7) + j];
}

// --- Stage E outputs ------------------------------------------------------
// e0 = (p0b - s)*inv_sq2; p0b = bP[0..), s = bB; also copy into bA
__global__ void __launch_bounds__(256) k_e0(float* __restrict__ out) {
    int idx = blockIdx.x * 256 + threadIdx.x;
    if (idx >= HM) return;
    int j = idx & 127, i = (idx >> 7) & 127, img = idx >> 14;
    float v = (bP[idx] - bB[idx]) * INV_SQ2;
    int b = img >> 7, ch = img & 127;
    long base = (ch < 64)
        ? (2L * SEG + ((long)((b << 6) + ch)      << 14))
        : (3L * SEG + ((long)((b << 6) + ch - 64) << 14));
    out[base + (i << 7) + j] = v;
    bA[idx] = v;
}
// e1 = -sq2*p1b - s; p1b = bP[HM..), s = bA
__global__ void __launch_bounds__(256) k_e1(float* __restrict__ out) {
    int idx = blockIdx.x * 256 + threadIdx.x;
    if (idx >= HM) return;
    int j = idx & 127, i = (idx >> 7) & 127, img = idx >> 14;
    float v = -SQ2 * bP[HM + idx] - bA[idx];
    int b = img >> 7, ch = img & 127;
    long base = (ch < 64)
        ? (1L * SEG + ((long)((b << 6) + ch)      << 14))
        : (4L * SEG + ((long)((b << 6) + ch - 64) << 14));
    out[base + (i << 7) + j] = v;
}

extern "C" void kernel_launch(void* const* d_in, const int* in_sizes, int n_in,
                              void* d_out, int out_size) {
    const float* x = (const float*)d_in[0];
    float* out = (float*)d_out;
    (void)in_sizes; (void)n_in; (void)out_size;

    const int T = 256;
    const int G4 = 4194304 / T, G8 = HM / T, G16 = FM / T;
    // z parked transiently in out segs 1-4 (consumed by resamp4 before e0/e1
    // overwrite those segments)
    float* zp = out + SEG;

    // --- c = sefilter2(x,h,h,'per')[::2,::2] -> seg0
    k_vh<<<G8, T>>>(x);                                  // x -> bA
    k_hh<<<G4, T>>>(out);                                // bA -> seg0
    // --- d = x - sefilter2(upsample(c), g, g, 'per')
    k_up<<<G16, T>>>(out);                               // seg0 -> bA (upsampled)
    conv_per<<<G16, T>>>(0, 0, 1, 0, 8, 8, 7, 3, 0, 1, FM);  // vert g: bA->bB
    conv_per<<<G16, T>>>(1, 0, 0, 0, 8, 8, 7, 3, 0, 0, FM);  // horz g: bB->bA
    k_sub<<<G16, T>>>(x);                                // d = x - bA -> bB
    // --- fbdec(d, f, '1r', 'qper_col')
    k_resamp2<<<G16, T>>>();                             // y: bB -> bA
    k_pp1<<<G8, T>>>();                                  // ye|p1pre: bA -> bB
    k_resamp3<<<G8, T>>>(0L,        0L);                 // p0 -> bP[0..)
    k_resamp3<<<G8, T>>>((long)HM,  (long)HM);           // p1 -> bP[HM..)
    k_vq<<<G8, T>>>(nullptr, 2, (long)HM, 6);            // sef(p1,(1,1)) vert -> bA
    conv_per<<<G8, T>>>(0, 0, 1, 0, 8, 7, 12, 6, 1, 0, HM);  // horz f: bA->bB
    k_y0c<<<G8, T>>>(zp);                                // y0a -> z0
    k_vq<<<G8, T>>>(zp, -1, 0L, 5);                      // sef(y0,(0,0)) vert -> bA
    conv_per<<<G8, T>>>(0, 0, 1, 0, 8, 7, 12, 5, 1, 0, HM);  // horz f: bA->bB
    k_y1c<<<G8, T>>>(zp + HM);                           // y1a -> z1
    // --- fbdec(z, f, '2c', 'per')
    k_resamp4<<<G16, T>>>(zp);                           // y4 -> bA
    k_pp2<<<G8, T>>>();                                  // pp0|pp1: bA -> bB
    k_resamp1<<<G8, T>>>(0L,        0L);                 // p0b -> bP[0..)
    k_resamp1<<<G8, T>>>((long)HM,  (long)HM);           // p1b -> bP[HM..)
    conv_per<<<G8, T>>>(2, (long)HM, 0, 0, 7, 7, 12, 6, 1, 1, HM); // vert f: p1b->bA
    conv_per<<<G8, T>>>(0, 0, 1, 0, 7, 7, 12, 6, 1, 0, HM);        // horz f: bA->bB
    k_e0<<<G8, T>>>(out);                                // e0 -> segs2/3 (+copy bA)
    conv_per<<<G8, T>>>(0, 0, 1, 0, 7, 7, 12, 5, 1, 1, HM);  // vert f: bA->bB
    conv_per<<<G8, T>>>(1, 0, 0, 0, 7, 7, 12, 5, 1, 0, HM);  // horz f: bB->bA
    k_e1<<<G8, T>>>(out);                                // e1 -> segs1/4
}

// round 9
// speedup vs baseline: 2.1823x; 2.1823x over previous
#include <cuda_runtime.h>

// ------- scratch: 3 x 64MB = 192MB; referenced ONLY from device code ------
static __device__ float bA[16777216];
static __device__ float bB[16777216];
static __device__ float bP[16777216];   // p0|p1 (stage D), then p0b|p1b (stage E)

// ---------------- filters ------------------------------------------------
__constant__ float c_h[9] = {
     0.037828455506995f, -0.02384946501938f, -0.11062440441842f,
     0.37740285561265f,   0.8526986790094f,   0.37740285561265f,
    -0.11062440441842f,  -0.02384946501938f,  0.037828455506995f };
__constant__ float c_g[7] = {
    -0.064538882628938f, -0.040689417609558f, 0.41809227322221f,
     0.78848561640566f,   0.41809227322221f, -0.040689417609558f,
    -0.064538882628938f };
__constant__ float c_f[12] = {
     0.0144f,  0.0272f,  0.0526f,  0.0972f,  0.193f,  0.63f,
    -0.63f,   -0.193f,  -0.0972f, -0.0526f, -0.0272f, -0.0144f };

#define INV_SQ2 0.7071067811865476f
#define SQ2     1.4142135623730951f
#define SEG     4194304L
#define HM 8388608
#define FM 16777216

// --- K1: vertical 9-tap h, stride-2 rows. x -> bA (256img,128,256) --------
__global__ void __launch_bounds__(256) k_vh(const float* __restrict__ x) {
    int idx = blockIdx.x * 256 + threadIdx.x;
    int j = idx & 255, i2 = (idx >> 8) & 127, img = idx >> 15;
    const float* xi = x + ((long)img << 16);
    float s = 0.f;
#pragma unroll
    for (int k = 0; k < 9; ++k)
        s = fmaf(c_h[k], xi[(((2 * i2 + k - 4) & 255) << 8) + j], s);
    bA[idx] = s;
}
// --- K2: horizontal 9-tap h, stride-2 cols. bA -> out seg0 (c) ------------
__global__ void __launch_bounds__(256) k_hh(float* __restrict__ outc) {
    int idx = blockIdx.x * 256 + threadIdx.x;
    int j = idx & 127, i = (idx >> 7) & 127, img = idx >> 14;
    const float* t = bA + ((long)img << 15) + (i << 8);
    float s = 0.f;
#pragma unroll
    for (int k = 0; k < 9; ++k)
        s = fmaf(c_h[k], t[(2 * j + k - 4) & 255], s);
    outc[idx] = s;
}

// --- K3: fused upsample + vertical g (odd result cols are 0; store even
//     cols only). c(out seg0) -> bA (256img, 256 rows, 128 evencols)
__global__ void __launch_bounds__(256) k_cvg(const float* __restrict__ cc) {
    int idx = blockIdx.x * 256 + threadIdx.x;
    int m = idx & 127, i = (idx >> 7) & 255, img = idx >> 15;
    const float* ci = cc + ((long)img << 14);
    float s = 0.f;
    if (i & 1) {   // (i+k-3) even requires k even
#pragma unroll
        for (int k = 0; k < 7; k += 2)
            s = fmaf(c_g[k], ci[((((i + k - 3) & 255) >> 1) << 7) + m], s);
    } else {       // k odd
#pragma unroll
        for (int k = 1; k < 7; k += 2)
            s = fmaf(c_g[k], ci[((((i + k - 3) & 255) >> 1) << 7) + m], s);
    }
    bA[idx] = s;
}
// --- K4: fused horizontal g + subtract: d = x - hconv(bA). -> bB ----------
__global__ void __launch_bounds__(256) k_chg_sub(const float* __restrict__ x) {
    int idx = blockIdx.x * 256 + threadIdx.x;
    int j = idx & 255, i = (idx >> 8) & 255, img = idx >> 16;
    const float* v = bA + ((long)img << 15) + (i << 7);
    float s = 0.f;
    if (j & 1) {   // (j+k-3) even requires k even
#pragma unroll
        for (int k = 0; k < 7; k += 2)
            s = fmaf(c_g[k], v[((j + k - 3) & 255) >> 1], s);
    } else {
#pragma unroll
        for (int k = 1; k < 7; k += 2)
            s = fmaf(c_g[k], v[((j + k - 3) & 255) >> 1], s);
    }
    bB[idx] = x[idx] - s;
}

// --- K5: stage-D quincunx. p0[i,j]=d[(i-j)%256,(i+j)%256]; p1 col+1 -------
// (mods distribute here: inner and outer both 256)
__global__ void __launch_bounds__(256) k_qp1() {
    int idx = blockIdx.x * 256 + threadIdx.x;
    int j = idx & 255, i = (idx >> 8) & 127, img = idx >> 15;
    const float* di = bB + ((long)img << 16) + (((i - j) & 255) << 8);
    bP[idx]      = di[(i + j) & 255];
    bP[HM + idx] = di[(i + j + 1) & 255];
}

// --- qper_col vertical 12-tap f on (128,256) -> bA ------------------------
template<int OFF, bool EXT>
__global__ void __launch_bounds__(256) k_vq(const float* __restrict__ ext) {
    int idx = blockIdx.x * 256 + threadIdx.x;
    int j = idx & 255, i = (idx >> 8) & 127, img = idx >> 15;
    const float* s = (EXT ? ext : (const float*)(bP + HM)) + ((long)img << 15);
    float a = 0.f;
#pragma unroll
    for (int k = 0; k < 12; ++k) {
        int r = i + k - OFF, sh = 0;
        if (r < 0)        { r += 128; sh = 128; }
        else if (r > 127) { r -= 128; sh = 128; }
        a = fmaf(c_f[k], s[(r << 8) + ((j + sh) & 255)], a);
    }
    bA[idx] = a;
}

// --- K7: fused horizontal f (off=6) + y0 combine -> zp --------------------
__global__ void __launch_bounds__(256) k_hf_y0(float* __restrict__ zp) {
    int idx = blockIdx.x * 256 + threadIdx.x;
    int j = idx & 255, i = (idx >> 8) & 127, img = idx >> 15;
    const float* t = bA + ((long)img << 15) + (i << 8);
    float a = 0.f;
#pragma unroll
    for (int k = 0; k < 12; ++k)
        a = fmaf(c_f[k], t[(j + k - 6) & 255], a);
    zp[idx] = (bP[idx] - a) * INV_SQ2;
}
// --- K9: fused horizontal f (off=5) + y1 combine -> zp1 -------------------
__global__ void __launch_bounds__(256) k_hf_y1(float* __restrict__ zp1) {
    int idx = blockIdx.x * 256 + threadIdx.x;
    int j = idx & 255, i = (idx >> 8) & 127, img = idx >> 15;
    const float* t = bA + ((long)img << 15) + (i << 8);
    float a = 0.f;
#pragma unroll
    for (int k = 0; k < 12; ++k)
        a = fmaf(c_f[k], t[(j + k - 5) & 255], a);
    zp1[idx] = -SQ2 * bP[HM + idx] - a;
}

// --- K10: stage-E quincunx (FIXED: inner mod-128 does NOT distribute
//     through outer mod-256).
// p0b[i,j] = z[(i+j)%128,      (2j   - (i+j)%128  ) % 256]
// p1b[i,j] = z[(i+j+1)%128,    (2j+1 - (i+j+1)%128) % 256]
// i.e. column = (j-i) + 128 when the row index wrapped.
__global__ void __launch_bounds__(256) k_qp2(const float* __restrict__ zp) {
    int idx = blockIdx.x * 256 + threadIdx.x;
    int j = idx & 127, i = (idx >> 7) & 127, img = idx >> 14;   // img in [0,512)
    int b = img >> 7, ch = img & 127;
    const float* zi = (ch < 64)
        ? (zp      + ((long)((b << 6) + ch)      << 15))
        : (zp + HM + ((long)((b << 6) + ch - 64) << 15));
    int a0 = i + j;
    int a1 = i + j + 1;
    int c0 = (j - i + ((a0 >> 7) << 7)) & 255;   // +128 iff a0 wrapped
    int c1 = (j - i + ((a1 >> 7) << 7)) & 255;   // +128 iff a1 wrapped
    bP[idx]      = zi[((a0 & 127) << 8) + c0];
    bP[HM + idx] = zi[((a1 & 127) << 8) + c1];
}

// --- periodic vertical 12-tap f on (128,128) -> bA ------------------------
// SRC=0: bP+HM (p1b); SRC=1: bB (e0 copy)
template<int OFF, int SRC>
__global__ void __launch_bounds__(256) k_vf() {
    int idx = blockIdx.x * 256 + threadIdx.x;
    int j = idx & 127, i = (idx >> 7) & 127, img = idx >> 14;
    const float* s = (SRC ? (const float*)bB : (const float*)(bP + HM))
                     + ((long)img << 14);
    float a = 0.f;
#pragma unroll
    for (int k = 0; k < 12; ++k)
        a = fmaf(c_f[k], s[(((i + k - OFF + 128) & 127) << 7) + j], a);
    bA[idx] = a;
}

// --- K12: fused horizontal f (off=6) + e0 combine -> out segs2/3 + bB -----
__global__ void __launch_bounds__(256) k_hf_e0(float* __restrict__ out) {
    int idx = blockIdx.x * 256 + threadIdx.x;
    int j = idx & 127, i = (idx >> 7) & 127, img = idx >> 14;
    const float* t = bA + ((long)img << 14) + (i << 7);
    float a = 0.f;
#pragma unroll
    for (int k = 0; k < 12; ++k)
        a = fmaf(c_f[k], t[(j + k - 6) & 127], a);
    float v = (bP[idx] - a) * INV_SQ2;
    int b = img >> 7, ch = img & 127;
    long base = (ch < 64)
        ? (2L * SEG + ((long)((b << 6) + ch)      << 14))
        : (3L * SEG + ((long)((b << 6) + ch - 64) << 14));
    out[base + (i << 7) + j] = v;
    bB[idx] = v;
}
// --- K14: fused horizontal f (off=5) + e1 combine -> out segs1/4 ----------
__global__ void __launch_bounds__(256) k_hf_e1(float* __restrict__ out) {
    int idx = blockIdx.x * 256 + threadIdx.x;
    int j = idx & 127, i = (idx >> 7) & 127, img = idx >> 14;
    const float* t = bA + ((long)img << 14) + (i << 7);
    float a = 0.f;
#pragma unroll
    for (int k = 0; k < 12; ++k)
        a = fmaf(c_f[k], t[(j + k - 5) & 127], a);
    float v = -SQ2 * bP[HM + idx] - a;
    int b = img >> 7, ch = img & 127;
    long base = (ch < 64)
        ? (1L * SEG + ((long)((b << 6) + ch)      << 14))
        : (4L * SEG + ((long)((b << 6) + ch - 64) << 14));
    out[base + (i << 7) + j] = v;
}

extern "C" void kernel_launch(void* const* d_in, const int* in_sizes, int n_in,
                              void* d_out, int out_size) {
    const float* x = (const float*)d_in[0];
    float* out = (float*)d_out;
    (void)in_sizes; (void)n_in; (void)out_size;

    const int T = 256;
    const int G4 = 4194304 / T, G8 = HM / T, G16 = FM / T;
    // z parked transiently in out segs 1-4 (consumed by k_qp2 before
    // e0/e1 overwrite those segments)
    float* zp = out + SEG;

    // c = sefilter2(x,h,h,'per')[::2,::2] -> seg0
    k_vh<<<G8, T>>>(x);
    k_hh<<<G4, T>>>(out);
    // d = x - sefilter2(upsample(c), g, g, 'per')  (parity-fused)
    k_cvg<<<G8, T>>>(out);
    k_chg_sub<<<G16, T>>>(x);
    // fbdec(d, f, '1r', 'qper_col')
    k_qp1<<<G8, T>>>();
    k_vq<6, false><<<G8, T>>>(nullptr);
    k_hf_y0<<<G8, T>>>(zp);
    k_vq<5, true><<<G8, T>>>(zp);
    k_hf_y1<<<G8, T>>>(zp + HM);
    // fbdec(z, f, '2c', 'per')
    k_qp2<<<G8, T>>>(zp);
    k_vf<6, 0><<<G8, T>>>();
    k_hf_e0<<<G8, T>>>(out);
    k_vf<5, 1><<<G8, T>>>();
    k_hf_e1<<<G8, T>>>(out);
}

// round 10
// speedup vs baseline: 4.7339x; 2.1692x over previous
#include <cuda_runtime.h>

// ------- scratch: 3 x 64MB = 192MB; referenced ONLY from device code ------
static __device__ float bA[16777216];
static __device__ float bB[16777216];
static __device__ float bP[16777216];   // p0|p1 (stage D), then p0b|p1b (stage E)

// ---------------- filters ------------------------------------------------
__constant__ float c_h[9] = {
     0.037828455506995f, -0.02384946501938f, -0.11062440441842f,
     0.37740285561265f,   0.8526986790094f,   0.37740285561265f,
    -0.11062440441842f,  -0.02384946501938f,  0.037828455506995f };
__constant__ float c_g[7] = {
    -0.064538882628938f, -0.040689417609558f, 0.41809227322221f,
     0.78848561640566f,   0.41809227322221f, -0.040689417609558f,
    -0.064538882628938f };
__constant__ float c_f[12] = {
     0.0144f,  0.0272f,  0.0526f,  0.0972f,  0.193f,  0.63f,
    -0.63f,   -0.193f,  -0.0972f, -0.0526f, -0.0272f, -0.0144f };

#define INV_SQ2 0.7071067811865476f
#define SQ2     1.4142135623730951f
#define SEG     4194304L
#define HM 8388608
#define FM 16777216

__device__ __forceinline__ float4 f4fma(float c, float4 v, float4 a) {
    a.x = fmaf(c, v.x, a.x); a.y = fmaf(c, v.y, a.y);
    a.z = fmaf(c, v.z, a.z); a.w = fmaf(c, v.w, a.w);
    return a;
}

// --- K1: vertical 9-tap h, stride-2 rows. x -> bA. 2M threads -------------
__global__ void __launch_bounds__(256) k_vh(const float* __restrict__ x) {
    int idx = blockIdx.x * 256 + threadIdx.x;
    int jb = idx & 63, i2 = (idx >> 6) & 127, img = idx >> 13;
    const float4* xi = (const float4*)x + ((long)img << 14);
    float4 s = {0.f, 0.f, 0.f, 0.f};
#pragma unroll
    for (int k = 0; k < 9; ++k)
        s = f4fma(c_h[k], xi[(((2 * i2 + k - 4) & 255) << 6) + jb], s);
    ((float4*)bA)[idx] = s;
}
// --- K2: horizontal 9-tap h, stride-2 cols. bA -> out seg0. 1M threads ----
__global__ void __launch_bounds__(256) k_hh(float* __restrict__ outc) {
    int idx = blockIdx.x * 256 + threadIdx.x;
    int jb = idx & 31, i = (idx >> 5) & 127, img = idx >> 12;
    const float4* t = (const float4*)bA + ((long)img << 13) + (i << 6);
    float r[20];
#pragma unroll
    for (int s = 0; s < 5; ++s) {
        float4 v = t[(2 * jb - 2 + s + 64) & 63];  // in[(8jb-8+4s+u)&255]
        r[4 * s] = v.x; r[4 * s + 1] = v.y; r[4 * s + 2] = v.z; r[4 * s + 3] = v.w;
    }
    float o[4];
#pragma unroll
    for (int m = 0; m < 4; ++m) {
        float s = 0.f;
#pragma unroll
        for (int k = 0; k < 9; ++k)
            s = fmaf(c_h[k], r[2 * m + k + 4], s);
        o[m] = s;
    }
    ((float4*)outc)[idx] = make_float4(o[0], o[1], o[2], o[3]);
}

// --- K3: fused upsample + vertical g (even cols only). seg0 -> bA. 2M -----
__global__ void __launch_bounds__(256) k_cvg(const float* __restrict__ cc) {
    int idx = blockIdx.x * 256 + threadIdx.x;
    int mb = idx & 31, i = (idx >> 5) & 255, img = idx >> 13;
    const float4* ci = (const float4*)cc + ((long)img << 12);
    float4 s = {0.f, 0.f, 0.f, 0.f};
    if (i & 1) {
#pragma unroll
        for (int k = 0; k < 7; k += 2)
            s = f4fma(c_g[k], ci[((((i + k - 3) & 255) >> 1) << 5) + mb], s);
    } else {
#pragma unroll
        for (int k = 1; k < 7; k += 2)
            s = f4fma(c_g[k], ci[((((i + k - 3) & 255) >> 1) << 5) + mb], s);
    }
    ((float4*)bA)[idx] = s;
}
// --- K4: fused horizontal g + subtract: d = x - hconv(bA) -> bB. 4M -------
__global__ void __launch_bounds__(256) k_chg_sub(const float* __restrict__ x) {
    int idx = blockIdx.x * 256 + threadIdx.x;
    int jb = idx & 63, i = (idx >> 6) & 255, img = idx >> 14;
    const float* v = bA + ((long)img << 15) + (i << 7);
    float o[4];
#pragma unroll
    for (int m = 0; m < 4; ++m) {
        int j = 4 * jb + m;
        float s = 0.f;
        if (m & 1) {   // j odd -> k even
#pragma unroll
            for (int k = 0; k < 7; k += 2)
                s = fmaf(c_g[k], v[((j + k - 3) & 255) >> 1], s);
        } else {       // j even -> k odd
#pragma unroll
            for (int k = 1; k < 7; k += 2)
                s = fmaf(c_g[k], v[((j + k - 3) & 255) >> 1], s);
        }
        o[m] = s;
    }
    float4 xv = ((const float4*)x)[idx];
    ((float4*)bB)[idx] =
        make_float4(xv.x - o[0], xv.y - o[1], xv.z - o[2], xv.w - o[3]);
}

// --- K5: stage-D quincunx. scalar gathers, float4 stores. 2M --------------
__global__ void __launch_bounds__(256) k_qp1() {
    int idx = blockIdx.x * 256 + threadIdx.x;
    int jb = idx & 63, i = (idx >> 6) & 127, img = idx >> 13;
    const float* di = bB + ((long)img << 16);
    float a[4], b[4];
#pragma unroll
    for (int m = 0; m < 4; ++m) {
        int j = 4 * jb + m;
        const float* rr = di + (((i - j) & 255) << 8);
        a[m] = rr[(i + j) & 255];
        b[m] = rr[(i + j + 1) & 255];
    }
    ((float4*)bP)[idx]        = make_float4(a[0], a[1], a[2], a[3]);
    ((float4*)(bP + HM))[idx] = make_float4(b[0], b[1], b[2], b[3]);
}

// --- qper_col vertical 12-tap f on (128,256) -> bA. 2M --------------------
template<int OFF, bool EXT>
__global__ void __launch_bounds__(256) k_vq(const float* __restrict__ ext) {
    int idx = blockIdx.x * 256 + threadIdx.x;
    int jb = idx & 63, i = (idx >> 6) & 127, img = idx >> 13;
    const float4* s4 = (EXT ? (const float4*)ext : (const float4*)(bP + HM))
                       + ((long)img << 13);
    float4 a = {0.f, 0.f, 0.f, 0.f};
#pragma unroll
    for (int k = 0; k < 12; ++k) {
        int r = i + k - OFF, sh = 0;
        if (r < 0)        { r += 128; sh = 32; }
        else if (r > 127) { r -= 128; sh = 32; }
        a = f4fma(c_f[k], s4[(r << 6) + ((jb + sh) & 63)], a);
    }
    ((float4*)bA)[idx] = a;
}

// --- K7/K9: fused horizontal f + y combine -> z. 2M each ------------------
template<int OFF>  // OFF=6: y0; OFF=5: y1
__global__ void __launch_bounds__(256) k_hf_y(float* __restrict__ zd) {
    int idx = blockIdx.x * 256 + threadIdx.x;
    int jb = idx & 63, i = (idx >> 6) & 127, img = idx >> 13;
    const float4* t = (const float4*)bA + ((long)img << 13) + (i << 6);
    float r[20];
#pragma unroll
    for (int s = 0; s < 5; ++s) {
        float4 v = t[(jb - 2 + s + 64) & 63];  // in[(4jb-8+4s+u)&255]
        r[4 * s] = v.x; r[4 * s + 1] = v.y; r[4 * s + 2] = v.z; r[4 * s + 3] = v.w;
    }
    float o[4];
#pragma unroll
    for (int m = 0; m < 4; ++m) {
        float s = 0.f;
#pragma unroll
        for (int k = 0; k < 12; ++k)
            s = fmaf(c_f[k], r[m + k + 8 - OFF], s);
        o[m] = s;
    }
    if (OFF == 6) {
        float4 p = ((const float4*)bP)[idx];
        ((float4*)zd)[idx] = make_float4((p.x - o[0]) * INV_SQ2,
                                         (p.y - o[1]) * INV_SQ2,
                                         (p.z - o[2]) * INV_SQ2,
                                         (p.w - o[3]) * INV_SQ2);
    } else {
        float4 p = ((const float4*)(bP + HM))[idx];
        ((float4*)zd)[idx] = make_float4(-SQ2 * p.x - o[0], -SQ2 * p.y - o[1],
                                         -SQ2 * p.z - o[2], -SQ2 * p.w - o[3]);
    }
}

// --- K10: stage-E quincunx (mod-128 inner / mod-256 outer). 2M ------------
__global__ void __launch_bounds__(256) k_qp2(const float* __restrict__ zp) {
    int idx = blockIdx.x * 256 + threadIdx.x;
    int jb = idx & 31, i = (idx >> 5) & 127, img = idx >> 12;   // img in [0,512)
    int b = img >> 7, ch = img & 127;
    const float* zi = (ch < 64)
        ? (zp      + ((long)((b << 6) + ch)      << 15))
        : (zp + HM + ((long)((b << 6) + ch - 64) << 15));
    float a[4], bb[4];
#pragma unroll
    for (int m = 0; m < 4; ++m) {
        int j = 4 * jb + m;
        int a0 = i + j, a1 = i + j + 1;
        int c0 = (j - i + ((a0 >> 7) << 7)) & 255;
        int c1 = (j - i + ((a1 >> 7) << 7)) & 255;
        a[m]  = zi[((a0 & 127) << 8) + c0];
        bb[m] = zi[((a1 & 127) << 8) + c1];
    }
    ((float4*)bP)[idx]        = make_float4(a[0], a[1], a[2], a[3]);
    ((float4*)(bP + HM))[idx] = make_float4(bb[0], bb[1], bb[2], bb[3]);
}

// --- periodic vertical 12-tap f on (128,128) -> bA. 2M --------------------
template<int OFF, int SRC>   // SRC=0: bP+HM (p1b); SRC=1: bB (e0)
__global__ void __launch_bounds__(256) k_vf() {
    int idx = blockIdx.x * 256 + threadIdx.x;
    int jb = idx & 31, i = (idx >> 5) & 127, img = idx >> 12;
    const float4* s4 = (SRC ? (const float4*)bB : (const float4*)(bP + HM))
                       + ((long)img << 12);
    float4 a = {0.f, 0.f, 0.f, 0.f};
#pragma unroll
    for (int k = 0; k < 12; ++k)
        a = f4fma(c_f[k], s4[(((i + k - OFF + 128) & 127) << 5) + jb], a);
    ((float4*)bA)[idx] = a;
}

// --- K12/K14: fused horizontal f + e combine -> out. 2M each --------------
template<int OFF>  // OFF=6: e0 (also copies to bB); OFF=5: e1
__global__ void __launch_bounds__(256) k_hf_e(float* __restrict__ out) {
    int idx = blockIdx.x * 256 + threadIdx.x;
    int jb = idx & 31, i = (idx >> 5) & 127, img = idx >> 12;
    const float4* t = (const float4*)bA + ((long)img << 12) + (i << 5);
    float r[20];
#pragma unroll
    for (int s = 0; s < 5; ++s) {
        float4 v = t[(jb - 2 + s + 32) & 31];  // in[(4jb-8+4s+u)&127]
        r[4 * s] = v.x; r[4 * s + 1] = v.y; r[4 * s + 2] = v.z; r[4 * s + 3] = v.w;
    }
    float o[4];
#pragma unroll
    for (int m = 0; m < 4; ++m) {
        float s = 0.f;
#pragma unroll
        for (int k = 0; k < 12; ++k)
            s = fmaf(c_f[k], r[m + k + 8 - OFF], s);
        o[m] = s;
    }
    int b = img >> 7, ch = img & 127;
    float4 res;
    if (OFF == 6) {
        float4 p = ((const float4*)bP)[idx];
        res = make_float4((p.x - o[0]) * INV_SQ2, (p.y - o[1]) * INV_SQ2,
                          (p.z - o[2]) * INV_SQ2, (p.w - o[3]) * INV_SQ2);
        ((float4*)bB)[idx] = res;
        long base4 = (ch < 64)
            ? (2L * (SEG / 4) + ((long)((b << 6) + ch)      << 12))
            : (3L * (SEG / 4) + ((long)((b << 6) + ch - 64) << 12));
        ((float4*)out)[base4 + (i << 5) + jb] = res;
    } else {
        float4 p = ((const float4*)(bP + HM))[idx];
        res = make_float4(-SQ2 * p.x - o[0], -SQ2 * p.y - o[1],
                          -SQ2 * p.z - o[2], -SQ2 * p.w - o[3]);
        long base4 = (ch < 64)
            ? (1L * (SEG / 4) + ((long)((b << 6) + ch)      << 12))
            : (4L * (SEG / 4) + ((long)((b << 6) + ch - 64) << 12));
        ((float4*)out)[base4 + (i << 5) + jb] = res;
    }
}

extern "C" void kernel_launch(void* const* d_in, const int* in_sizes, int n_in,
                              void* d_out, int out_size) {
    const float* x = (const float*)d_in[0];
    float* out = (float*)d_out;
    (void)in_sizes; (void)n_in; (void)out_size;

    const int T = 256;
    const int G1 = 1048576 / T, G2 = 2097152 / T, G4m = 4194304 / T;
    // z parked transiently in out segs 1-4 (consumed by k_qp2 before
    // e0/e1 overwrite those segments)
    float* zp = out + SEG;

    // c = sefilter2(x,h,h,'per')[::2,::2] -> seg0
    k_vh<<<G2, T>>>(x);
    k_hh<<<G1, T>>>(out);
    // d = x - sefilter2(upsample(c), g, g, 'per')
    k_cvg<<<G2, T>>>(out);
    k_chg_sub<<<G4m, T>>>(x);
    // fbdec(d, f, '1r', 'qper_col')
    k_qp1<<<G2, T>>>();
    k_vq<6, false><<<G2, T>>>(nullptr);
    k_hf_y<6><<<G2, T>>>(zp);
    k_vq<5, true><<<G2, T>>>(zp);
    k_hf_y<5><<<G2, T>>>(zp + HM);
    // fbdec(z, f, '2c', 'per')
    k_qp2<<<G2, T>>>(zp);
    k_vf<6, 0><<<G2, T>>>();
    k_hf_e<6><<<G2, T>>>(out);
    k_vf<5, 1><<<G2, T>>>();
    k_hf_e<5><<<G2, T>>>(out);
}

// round 11
// speedup vs baseline: 4.8462x; 1.0237x over previous
#include <cuda_runtime.h>

// ------- scratch: 3 x 64MB = 192MB; referenced ONLY from device code ------
static __device__ float bA[16777216];   // (mostly unused now; kept for safety)
static __device__ float bB[16777216];   // d (stage C/D); e0 copy (stage E)
static __device__ float bP[16777216];   // p0|p1 (stage D), then p0b|p1b (stage E)

// ---------------- filters ------------------------------------------------
__constant__ float c_h[9] = {
     0.037828455506995f, -0.02384946501938f, -0.11062440441842f,
     0.37740285561265f,   0.8526986790094f,   0.37740285561265f,
    -0.11062440441842f,  -0.02384946501938f,  0.037828455506995f };
__constant__ float c_g[7] = {
    -0.064538882628938f, -0.040689417609558f, 0.41809227322221f,
     0.78848561640566f,   0.41809227322221f, -0.040689417609558f,
    -0.064538882628938f };
__constant__ float c_f[12] = {
     0.0144f,  0.0272f,  0.0526f,  0.0972f,  0.193f,  0.63f,
    -0.63f,   -0.193f,  -0.0972f, -0.0526f, -0.0272f, -0.0144f };

#define INV_SQ2 0.7071067811865476f
#define SQ2     1.4142135623730951f
#define SEG     4194304L
#define HM 8388608

__device__ __forceinline__ float4 f4fma(float c, float4 v, float4 a) {
    a.x = fmaf(c, v.x, a.x); a.y = fmaf(c, v.y, a.y);
    a.z = fmaf(c, v.z, a.z); a.w = fmaf(c, v.w, a.w);
    return a;
}

// ===== K_AB: fused (vertical h, stride-2 rows) + (horizontal h, stride-2
//       cols). x -> out seg0 (c). grid = 256 img x 4 rowblocks ==============
__global__ void __launch_bounds__(256) k_AB(const float* __restrict__ x,
                                            float* __restrict__ outc) {
    __shared__ float4 t[2048];          // 32 rows x 64 f4 cols (vh output)
    int rb = blockIdx.x & 3, img = blockIdx.x >> 2;
    int tid = threadIdx.x;
    const float4* xi = (const float4*)x + ((long)img << 14);
    // phase 1: vh rows [rb*32, rb*32+32)
    {
        int jb = tid & 63, ib = tid >> 6;
        for (int rr = ib; rr < 32; rr += 4) {
            int i2 = rb * 32 + rr;
            float4 s = {0.f, 0.f, 0.f, 0.f};
#pragma unroll
            for (int k = 0; k < 9; ++k)
                s = f4fma(c_h[k], xi[(((2 * i2 + k - 4) & 255) << 6) + jb], s);
            t[rr * 64 + jb] = s;
        }
    }
    __syncthreads();
    // phase 2: hh on smem rows -> 32 f4 outputs per row
    {
        int jb = tid & 31, ib = tid >> 5;
        for (int rr = ib; rr < 32; rr += 8) {
            const float4* trow = t + rr * 64;
            float r[20];
#pragma unroll
            for (int s = 0; s < 5; ++s) {
                float4 v = trow[(2 * jb - 2 + s + 64) & 63];
                r[4*s] = v.x; r[4*s+1] = v.y; r[4*s+2] = v.z; r[4*s+3] = v.w;
            }
            float o[4];
#pragma unroll
            for (int m = 0; m < 4; ++m) {
                float s = 0.f;
#pragma unroll
                for (int k = 0; k < 9; ++k)
                    s = fmaf(c_h[k], r[2 * m + k + 4], s);
                o[m] = s;
            }
            int i = rb * 32 + rr;
            ((float4*)outc)[((long)img << 12) + (i << 5) + jb] =
                make_float4(o[0], o[1], o[2], o[3]);
        }
    }
}

// ===== K_C: fused (upsample+vertical g, even cols) + (horizontal g + sub).
//       c(seg0), x -> bB = d. grid = 256 img x 8 rowblocks ==================
__global__ void __launch_bounds__(256) k_C(const float* __restrict__ cc,
                                           const float* __restrict__ x) {
    __shared__ float v[4096];           // 32 rows x 128 evencols
    int rb = blockIdx.x & 7, img = blockIdx.x >> 3;
    int tid = threadIdx.x;
    const float4* ci = (const float4*)cc + ((long)img << 12);
    // phase 1: cvg rows [rb*32, rb*32+32), 32 f4 cols
    {
        int jb = tid & 31, ib = tid >> 5;
        for (int rr = ib; rr < 32; rr += 8) {
            int i = rb * 32 + rr;
            float4 s = {0.f, 0.f, 0.f, 0.f};
            if (i & 1) {
#pragma unroll
                for (int k = 0; k < 7; k += 2)
                    s = f4fma(c_g[k], ci[((((i + k - 3) & 255) >> 1) << 5) + jb], s);
            } else {
#pragma unroll
                for (int k = 1; k < 7; k += 2)
                    s = f4fma(c_g[k], ci[((((i + k - 3) & 255) >> 1) << 5) + jb], s);
            }
            ((float4*)v)[rr * 32 + jb] = s;
        }
    }
    __syncthreads();
    // phase 2: horizontal g + subtract -> bB
    {
        int jb = tid & 63, ib = tid >> 6;
        for (int rr = ib; rr < 32; rr += 4) {
            int i = rb * 32 + rr;
            const float* vr = v + rr * 128;
            float o[4];
#pragma unroll
            for (int m = 0; m < 4; ++m) {
                int j = 4 * jb + m;
                float s = 0.f;
                if (m & 1) {
#pragma unroll
                    for (int k = 0; k < 7; k += 2)
                        s = fmaf(c_g[k], vr[((j + k - 3) & 255) >> 1], s);
                } else {
#pragma unroll
                    for (int k = 1; k < 7; k += 2)
                        s = fmaf(c_g[k], vr[((j + k - 3) & 255) >> 1], s);
                }
                o[m] = s;
            }
            long fi = ((long)img << 14) + (i << 6) + jb;
            float4 xv = ((const float4*)x)[fi];
            ((float4*)bB)[fi] =
                make_float4(xv.x - o[0], xv.y - o[1], xv.z - o[2], xv.w - o[3]);
        }
    }
}

// ===== K5: stage-D quincunx. bB(d) -> bP(p0) | bP+HM(p1). 2M threads ======
__global__ void __launch_bounds__(256) k_qp1() {
    int idx = blockIdx.x * 256 + threadIdx.x;
    int jb = idx & 63, i = (idx >> 6) & 127, img = idx >> 13;
    const float* di = bB + ((long)img << 16);
    float a[4], b[4];
#pragma unroll
    for (int m = 0; m < 4; ++m) {
        int j = 4 * jb + m;
        const float* rr = di + (((i - j) & 255) << 8);
        a[m] = rr[(i + j) & 255];
        b[m] = rr[(i + j + 1) & 255];
    }
    ((float4*)bP)[idx]        = make_float4(a[0], a[1], a[2], a[3]);
    ((float4*)(bP + HM))[idx] = make_float4(b[0], b[1], b[2], b[3]);
}

// ===== K_D: fused qper_col vertical f + horizontal f + ladder combine.
//       images (128,256). grid = 256 img x 4 rowblocks.
//  OFF=6: src=bP+HM(p1), comb=bP(p0), dst=zp      (y0a)
//  OFF=5: src=zp(y0a ext), comb=bP+HM(p1), dst=zp1 (y1a) ====================
template<int OFF, bool EXT>
__global__ void __launch_bounds__(256) k_D(const float* __restrict__ ext,
                                           float* __restrict__ dst) {
    __shared__ float4 t[2048];          // 32 rows x 64 f4 cols
    int rb = blockIdx.x & 3, img = blockIdx.x >> 2;
    int tid = threadIdx.x;
    const float4* s4 = (EXT ? (const float4*)ext : (const float4*)(bP + HM))
                       + ((long)img << 13);
    // phase 1: vertical f with qper_col wrap
    {
        int jb = tid & 63, ib = tid >> 6;
        for (int rr = ib; rr < 32; rr += 4) {
            int i = rb * 32 + rr;
            float4 a = {0.f, 0.f, 0.f, 0.f};
#pragma unroll
            for (int k = 0; k < 12; ++k) {
                int r = i + k - OFF, sh = 0;
                if (r < 0)        { r += 128; sh = 32; }
                else if (r > 127) { r -= 128; sh = 32; }
                a = f4fma(c_f[k], s4[(r << 6) + ((jb + sh) & 63)], a);
            }
            t[rr * 64 + jb] = a;
        }
    }
    __syncthreads();
    // phase 2: horizontal f + combine
    {
        int jb = tid & 63, ib = tid >> 6;
        for (int rr = ib; rr < 32; rr += 4) {
            const float4* trow = t + rr * 64;
            float r[20];
#pragma unroll
            for (int s = 0; s < 5; ++s) {
                float4 v = trow[(jb - 2 + s + 64) & 63];
                r[4*s] = v.x; r[4*s+1] = v.y; r[4*s+2] = v.z; r[4*s+3] = v.w;
            }
            float o[4];
#pragma unroll
            for (int m = 0; m < 4; ++m) {
                float s = 0.f;
#pragma unroll
                for (int k = 0; k < 12; ++k)
                    s = fmaf(c_f[k], r[m + k + 8 - OFF], s);
                o[m] = s;
            }
            int i = rb * 32 + rr;
            long fi = ((long)img << 13) + (i << 6) + jb;
            if (OFF == 6) {
                float4 p = ((const float4*)bP)[fi];
                ((float4*)dst)[fi] = make_float4((p.x - o[0]) * INV_SQ2,
                                                 (p.y - o[1]) * INV_SQ2,
                                                 (p.z - o[2]) * INV_SQ2,
                                                 (p.w - o[3]) * INV_SQ2);
            } else {
                float4 p = ((const float4*)(bP + HM))[fi];
                ((float4*)dst)[fi] = make_float4(-SQ2 * p.x - o[0],
                                                 -SQ2 * p.y - o[1],
                                                 -SQ2 * p.z - o[2],
                                                 -SQ2 * p.w - o[3]);
            }
        }
    }
}

// ===== K10: stage-E quincunx. z(zp) -> bP(p0b) | bP+HM(p1b). 2M ===========
__global__ void __launch_bounds__(256) k_qp2(const float* __restrict__ zp) {
    int idx = blockIdx.x * 256 + threadIdx.x;
    int jb = idx & 31, i = (idx >> 5) & 127, img = idx >> 12;   // img in [0,512)
    int b = img >> 7, ch = img & 127;
    const float* zi = (ch < 64)
        ? (zp      + ((long)((b << 6) + ch)      << 15))
        : (zp + HM + ((long)((b << 6) + ch - 64) << 15));
    float a[4], bb[4];
#pragma unroll
    for (int m = 0; m < 4; ++m) {
        int j = 4 * jb + m;
        int a0 = i + j, a1 = i + j + 1;
        int c0 = (j - i + ((a0 >> 7) << 7)) & 255;
        int c1 = (j - i + ((a1 >> 7) << 7)) & 255;
        a[m]  = zi[((a0 & 127) << 8) + c0];
        bb[m] = zi[((a1 & 127) << 8) + c1];
    }
    ((float4*)bP)[idx]        = make_float4(a[0], a[1], a[2], a[3]);
    ((float4*)(bP + HM))[idx] = make_float4(bb[0], bb[1], bb[2], bb[3]);
}

// ===== K_E: fused periodic vertical f + horizontal f + combine.
//       images (128,128). grid = 512 img x 4 rowblocks.
//  OFF=6 (SRC=0): src=bP+HM(p1b), comb=bP(p0b) -> out segs2/3 + bB copy
//  OFF=5 (SRC=1): src=bB(e0),     comb=bP+HM   -> out segs1/4 ==============
template<int OFF, int SRC>
__global__ void __launch_bounds__(256) k_E(float* __restrict__ out) {
    __shared__ float4 t[1024];          // 32 rows x 32 f4 cols
    int rb = blockIdx.x & 3, img = blockIdx.x >> 2;
    int tid = threadIdx.x;
    const float4* s4 = (SRC ? (const float4*)bB : (const float4*)(bP + HM))
                       + ((long)img << 12);
    // phase 1: vertical f, periodic rows mod 128
    {
        int jb = tid & 31, ib = tid >> 5;
        for (int rr = ib; rr < 32; rr += 8) {
            int i = rb * 32 + rr;
            float4 a = {0.f, 0.f, 0.f, 0.f};
#pragma unroll
            for (int k = 0; k < 12; ++k)
                a = f4fma(c_f[k], s4[(((i + k - OFF + 128) & 127) << 5) + jb], a);
            t[rr * 32 + jb] = a;
        }
    }
    __syncthreads();
    // phase 2: horizontal f + combine -> out
    {
        int jb = tid & 31, ib = tid >> 5;
        int b = img >> 7, ch = img & 127;
        for (int rr = ib; rr < 32; rr += 8) {
            const float4* trow = t + rr * 32;
            float r[20];
#pragma unroll
            for (int s = 0; s < 5; ++s) {
                float4 v = trow[(jb - 2 + s + 32) & 31];
                r[4*s] = v.x; r[4*s+1] = v.y; r[4*s+2] = v.z; r[4*s+3] = v.w;
            }
            float o[4];
#pragma unroll
            for (int m = 0; m < 4; ++m) {
                float s = 0.f;
#pragma unroll
                for (int k = 0; k < 12; ++k)
                    s = fmaf(c_f[k], r[m + k + 8 - OFF], s);
                o[m] = s;
            }
            int i = rb * 32 + rr;
            long fi = ((long)img << 12) + (i << 5) + jb;
            if (OFF == 6) {
                float4 p = ((const float4*)bP)[fi];
                float4 res = make_float4((p.x - o[0]) * INV_SQ2,
                                         (p.y - o[1]) * INV_SQ2,
                                         (p.z - o[2]) * INV_SQ2,
                                         (p.w - o[3]) * INV_SQ2);
                ((float4*)bB)[fi] = res;
                long base4 = (ch < 64)
                    ? (2L * (SEG / 4) + ((long)((b << 6) + ch)      << 12))
                    : (3L * (SEG / 4) + ((long)((b << 6) + ch - 64) << 12));
                ((float4*)out)[base4 + (i << 5) + jb] = res;
            } else {
                float4 p = ((const float4*)(bP + HM))[fi];
                float4 res = make_float4(-SQ2 * p.x - o[0], -SQ2 * p.y - o[1],
                                         -SQ2 * p.z - o[2], -SQ2 * p.w - o[3]);
                long base4 = (ch < 64)
                    ? (1L * (SEG / 4) + ((long)((b << 6) + ch)      << 12))
                    : (4L * (SEG / 4) + ((long)((b << 6) + ch - 64) << 12));
                ((float4*)out)[base4 + (i << 5) + jb] = res;
            }
        }
    }
}

extern "C" void kernel_launch(void* const* d_in, const int* in_sizes, int n_in,
                              void* d_out, int out_size) {
    const float* x = (const float*)d_in[0];
    float* out = (float*)d_out;
    (void)in_sizes; (void)n_in; (void)out_size; (void)bA;

    const int T = 256;
    // z parked transiently in out segs 1-4 (consumed by k_qp2 before
    // e0/e1 overwrite those segments)
    float* zp = out + SEG;

    k_AB<<<1024, T>>>(x, out);            // c -> seg0
    k_C<<<2048, T>>>(out, x);             // d -> bB
    k_qp1<<<8192, T>>>();                 // p0|p1 -> bP
    k_D<6, false><<<1024, T>>>(nullptr, zp);        // y0a -> z0
    k_D<5, true ><<<1024, T>>>(zp, zp + HM);        // y1a -> z1
    k_qp2<<<8192, T>>>(zp);               // p0b|p1b -> bP
    k_E<6, 0><<<2048, T>>>(out);          // e0 -> segs2/3 (+bB copy)
    k_E<5, 1><<<2048, T>>>(out);          // e1 -> segs1/4
}

// round 12
// speedup vs baseline: 5.6982x; 1.1758x over previous
#include <cuda_runtime.h>

// ------- scratch: 3 x 64MB = 192MB; referenced ONLY from device code ------
static __device__ float bA[16777216];   // z0 | z1 (stage D outputs)
static __device__ float bB[16777216];   // d (stage C/D)
static __device__ float bP[16777216];   // p0|p1 (stage D), then p0b|p1b (stage E)

// ---------------- filters ------------------------------------------------
__constant__ float c_h[9] = {
     0.037828455506995f, -0.02384946501938f, -0.11062440441842f,
     0.37740285561265f,   0.8526986790094f,   0.37740285561265f,
    -0.11062440441842f,  -0.02384946501938f,  0.037828455506995f };
__constant__ float c_g[7] = {
    -0.064538882628938f, -0.040689417609558f, 0.41809227322221f,
     0.78848561640566f,   0.41809227322221f, -0.040689417609558f,
    -0.064538882628938f };
__constant__ float c_f[12] = {
     0.0144f,  0.0272f,  0.0526f,  0.0972f,  0.193f,  0.63f,
    -0.63f,   -0.193f,  -0.0972f, -0.0526f, -0.0272f, -0.0144f };

#define INV_SQ2 0.7071067811865476f
#define SQ2     1.4142135623730951f
#define SEG     4194304L
#define HM 8388608

__device__ __forceinline__ float4 f4fma(float c, float4 v, float4 a) {
    a.x = fmaf(c, v.x, a.x); a.y = fmaf(c, v.y, a.y);
    a.z = fmaf(c, v.z, a.z); a.w = fmaf(c, v.w, a.w);
    return a;
}

// ===== K_AB: fused vh(stride2) + hh(stride2). x -> out seg0 (c) ===========
__global__ void __launch_bounds__(256) k_AB(const float* __restrict__ x,
                                            float* __restrict__ outc) {
    __shared__ float4 t[2048];          // 32 rows x 64 f4
    int rb = blockIdx.x & 3, img = blockIdx.x >> 2;
    int tid = threadIdx.x;
    const float4* xi = (const float4*)x + ((long)img << 14);
    {
        int jb = tid & 63, ib = tid >> 6;
        for (int rr = ib; rr < 32; rr += 4) {
            int i2 = rb * 32 + rr;
            float4 s = {0.f, 0.f, 0.f, 0.f};
#pragma unroll
            for (int k = 0; k < 9; ++k)
                s = f4fma(c_h[k], xi[(((2 * i2 + k - 4) & 255) << 6) + jb], s);
            t[rr * 64 + jb] = s;
        }
    }
    __syncthreads();
    {
        int jb = tid & 31, ib = tid >> 5;
        for (int rr = ib; rr < 32; rr += 8) {
            const float4* trow = t + rr * 64;
            float r[20];
#pragma unroll
            for (int s = 0; s < 5; ++s) {
                float4 v = trow[(2 * jb - 2 + s + 64) & 63];
                r[4*s] = v.x; r[4*s+1] = v.y; r[4*s+2] = v.z; r[4*s+3] = v.w;
            }
            float o[4];
#pragma unroll
            for (int m = 0; m < 4; ++m) {
                float s = 0.f;
#pragma unroll
                for (int k = 0; k < 9; ++k)
                    s = fmaf(c_h[k], r[2 * m + k + 4], s);
                o[m] = s;
            }
            int i = rb * 32 + rr;
            ((float4*)outc)[((long)img << 12) + (i << 5) + jb] =
                make_float4(o[0], o[1], o[2], o[3]);
        }
    }
}

// ===== K_C: fused (upsample+vert g) + (horiz g + sub). c,x -> bB = d ======
__global__ void __launch_bounds__(256) k_C(const float* __restrict__ cc,
                                           const float* __restrict__ x) {
    __shared__ float v[4096];           // 32 rows x 128 evencols
    int rb = blockIdx.x & 7, img = blockIdx.x >> 3;
    int tid = threadIdx.x;
    const float4* ci = (const float4*)cc + ((long)img << 12);
    {
        int jb = tid & 31, ib = tid >> 5;
        for (int rr = ib; rr < 32; rr += 8) {
            int i = rb * 32 + rr;
            float4 s = {0.f, 0.f, 0.f, 0.f};
            if (i & 1) {
#pragma unroll
                for (int k = 0; k < 7; k += 2)
                    s = f4fma(c_g[k], ci[((((i + k - 3) & 255) >> 1) << 5) + jb], s);
            } else {
#pragma unroll
                for (int k = 1; k < 7; k += 2)
                    s = f4fma(c_g[k], ci[((((i + k - 3) & 255) >> 1) << 5) + jb], s);
            }
            ((float4*)v)[rr * 32 + jb] = s;
        }
    }
    __syncthreads();
    {
        int jb = tid & 63, ib = tid >> 6;
        for (int rr = ib; rr < 32; rr += 4) {
            int i = rb * 32 + rr;
            const float* vr = v + rr * 128;
            float o[4];
#pragma unroll
            for (int m = 0; m < 4; ++m) {
                int j = 4 * jb + m;
                float s = 0.f;
                if (m & 1) {
#pragma unroll
                    for (int k = 0; k < 7; k += 2)
                        s = fmaf(c_g[k], vr[((j + k - 3) & 255) >> 1], s);
                } else {
#pragma unroll
                    for (int k = 1; k < 7; k += 2)
                        s = fmaf(c_g[k], vr[((j + k - 3) & 255) >> 1], s);
                }
                o[m] = s;
            }
            long fi = ((long)img << 14) + (i << 6) + jb;
            float4 xv = ((const float4*)x)[fi];
            ((float4*)bB)[fi] =
                make_float4(xv.x - o[0], xv.y - o[1], xv.z - o[2], xv.w - o[3]);
        }
    }
}

// ===== K5: stage-D quincunx. bB(d) -> bP(p0) | bP+HM(p1) ===================
__global__ void __launch_bounds__(256) k_qp1() {
    int idx = blockIdx.x * 256 + threadIdx.x;
    int jb = idx & 63, i = (idx >> 6) & 127, img = idx >> 13;
    const float* di = bB + ((long)img << 16);
    float a[4], b[4];
#pragma unroll
    for (int m = 0; m < 4; ++m) {
        int j = 4 * jb + m;
        const float* rr = di + (((i - j) & 255) << 8);
        a[m] = rr[(i + j) & 255];
        b[m] = rr[(i + j + 1) & 255];
    }
    ((float4*)bP)[idx]        = make_float4(a[0], a[1], a[2], a[3]);
    ((float4*)(bP + HM))[idx] = make_float4(b[0], b[1], b[2], b[3]);
}

// ===== K_D: sliding-window qper_col vert f + horiz f + combine.
//  (128,256) images. grid = 256 img x 4 rowblocks. SRC 0: p1(bP+HM); 1: z0(bA)
//  OFF=6: comb p0(bP)    -> z0 (bA[0..HM))
//  OFF=5: comb p1(bP+HM) -> z1 (bA[HM..)) =================================
template<int OFF, int SRC>
__global__ void __launch_bounds__(256) k_D() {
    __shared__ float4 t[2048];          // 32 rows x 64 f4
    int rb = blockIdx.x & 3, img = blockIdx.x >> 2;
    int tid = threadIdx.x;
    const float4* s4 = (SRC ? (const float4*)bA : (const float4*)(bP + HM))
                       + ((long)img << 13);
    // phase 1: vertical 12-tap f, 8 consecutive rows per thread
    {
        int jb = tid & 63, strip = tid >> 6;
        int r0 = rb * 32 + strip * 8;
        float4 acc[8];
#pragma unroll
        for (int q = 0; q < 8; ++q) acc[q] = make_float4(0.f, 0.f, 0.f, 0.f);
#pragma unroll
        for (int s = 0; s < 19; ++s) {
            int a = r0 - OFF + s;
            int row = a, col = jb;
            if (a < 0)        { row = a + 128; col = (jb + 32) & 63; }
            else if (a > 127) { row = a - 128; col = (jb + 32) & 63; }
            float4 v = s4[(row << 6) + col];
#pragma unroll
            for (int q = 0; q < 8; ++q) {
                int k = s - q;
                if (k >= 0 && k < 12) acc[q] = f4fma(c_f[k], v, acc[q]);
            }
        }
#pragma unroll
        for (int q = 0; q < 8; ++q)
            t[(strip * 8 + q) * 64 + jb] = acc[q];
    }
    __syncthreads();
    // phase 2: horizontal f + combine
    {
        int jb = tid & 63, ib = tid >> 6;
        for (int rr = ib; rr < 32; rr += 4) {
            const float4* trow = t + rr * 64;
            float r[20];
#pragma unroll
            for (int s = 0; s < 5; ++s) {
                float4 v = trow[(jb - 2 + s + 64) & 63];
                r[4*s] = v.x; r[4*s+1] = v.y; r[4*s+2] = v.z; r[4*s+3] = v.w;
            }
            float o[4];
#pragma unroll
            for (int m = 0; m < 4; ++m) {
                float s = 0.f;
#pragma unroll
                for (int k = 0; k < 12; ++k)
                    s = fmaf(c_f[k], r[m + k + 8 - OFF], s);
                o[m] = s;
            }
            int i = rb * 32 + rr;
            long fi = ((long)img << 13) + (i << 6) + jb;
            if (OFF == 6) {
                float4 p = ((const float4*)bP)[fi];
                ((float4*)bA)[fi] = make_float4((p.x - o[0]) * INV_SQ2,
                                                (p.y - o[1]) * INV_SQ2,
                                                (p.z - o[2]) * INV_SQ2,
                                                (p.w - o[3]) * INV_SQ2);
            } else {
                float4 p = ((const float4*)(bP + HM))[fi];
                ((float4*)(bA + HM))[fi] = make_float4(-SQ2 * p.x - o[0],
                                                       -SQ2 * p.y - o[1],
                                                       -SQ2 * p.z - o[2],
                                                       -SQ2 * p.w - o[3]);
            }
        }
    }
}

// ===== K10: stage-E quincunx. bA(z) -> bP(p0b) | bP+HM(p1b) ===============
__global__ void __launch_bounds__(256) k_qp2() {
    int idx = blockIdx.x * 256 + threadIdx.x;
    int jb = idx & 31, i = (idx >> 5) & 127, img = idx >> 12;   // img in [0,512)
    int b = img >> 7, ch = img & 127;
    const float* zi = (ch < 64)
        ? (bA      + ((long)((b << 6) + ch)      << 15))
        : (bA + HM + ((long)((b << 6) + ch - 64) << 15));
    float a[4], bb[4];
#pragma unroll
    for (int m = 0; m < 4; ++m) {
        int j = 4 * jb + m;
        int a0 = i + j, a1 = i + j + 1;
        int c0 = (j - i + ((a0 >> 7) << 7)) & 255;
        int c1 = (j - i + ((a1 >> 7) << 7)) & 255;
        a[m]  = zi[((a0 & 127) << 8) + c0];
        bb[m] = zi[((a1 & 127) << 8) + c1];
    }
    ((float4*)bP)[idx]        = make_float4(a[0], a[1], a[2], a[3]);
    ((float4*)(bP + HM))[idx] = make_float4(bb[0], bb[1], bb[2], bb[3]);
}

// ===== K_E: sliding-window periodic vert f + horiz f + combine.
//  (128,128) images. grid = 512 img x 2 rowblocks (64 rows each).
//  OFF=6 (SRC=0): vert p1b(bP+HM), comb p0b(bP) -> out segs2/3
//  OFF=5 (SRC=1): vert e0 (read from out),  comb p1b     -> out segs1/4 ====
template<int OFF, int SRC>
__global__ void __launch_bounds__(256) k_E(float* __restrict__ out) {
    __shared__ float4 t[2048];          // 64 rows x 32 f4
    int rb = blockIdx.x & 1, img = blockIdx.x >> 1;
    int tid = threadIdx.x;
    int b = img >> 7, ch = img & 127;
    const float4* s4;
    if (SRC) {
        long base4 = (ch < 64)
            ? (2L * (SEG / 4) + ((long)((b << 6) + ch)      << 12))
            : (3L * (SEG / 4) + ((long)((b << 6) + ch - 64) << 12));
        s4 = (const float4*)out + base4;
    } else {
        s4 = (const float4*)(bP + HM) + ((long)img << 12);
    }
    // phase 1: vertical 12-tap f (periodic rows), 8 consecutive rows/thread
    {
        int jb = tid & 31, strip = tid >> 5;
        int r0 = rb * 64 + strip * 8;
        float4 acc[8];
#pragma unroll
        for (int q = 0; q < 8; ++q) acc[q] = make_float4(0.f, 0.f, 0.f, 0.f);
#pragma unroll
        for (int s = 0; s < 19; ++s) {
            int row = (r0 - OFF + s + 128) & 127;
            float4 v = s4[(row << 5) + jb];
#pragma unroll
            for (int q = 0; q < 8; ++q) {
                int k = s - q;
                if (k >= 0 && k < 12) acc[q] = f4fma(c_f[k], v, acc[q]);
            }
        }
#pragma unroll
        for (int q = 0; q < 8; ++q)
            t[(strip * 8 + q) * 32 + jb] = acc[q];
    }
    __syncthreads();
    // phase 2: horizontal f + combine -> out
    {
        int jb = tid & 31, ib = tid >> 5;
        for (int rr = ib; rr < 64; rr += 8) {
            const float4* trow = t + rr * 32;
            float r[20];
#pragma unroll
            for (int s = 0; s < 5; ++s) {
                float4 v = trow[(jb - 2 + s + 32) & 31];
                r[4*s] = v.x; r[4*s+1] = v.y; r[4*s+2] = v.z; r[4*s+3] = v.w;
            }
            float o[4];
#pragma unroll
            for (int m = 0; m < 4; ++m) {
                float s = 0.f;
#pragma unroll
                for (int k = 0; k < 12; ++k)
                    s = fmaf(c_f[k], r[m + k + 8 - OFF], s);
                o[m] = s;
            }
            int i = rb * 64 + rr;
            long fi = ((long)img << 12) + (i << 5) + jb;
            if (OFF == 6) {
                float4 p = ((const float4*)bP)[fi];
                float4 res = make_float4((p.x - o[0]) * INV_SQ2,
                                         (p.y - o[1]) * INV_SQ2,
                                         (p.z - o[2]) * INV_SQ2,
                                         (p.w - o[3]) * INV_SQ2);
                long base4 = (ch < 64)
                    ? (2L * (SEG / 4) + ((long)((b << 6) + ch)      << 12))
                    : (3L * (SEG / 4) + ((long)((b << 6) + ch - 64) << 12));
                ((float4*)out)[base4 + (i << 5) + jb] = res;
            } else {
                float4 p = ((const float4*)(bP + HM))[fi];
                float4 res = make_float4(-SQ2 * p.x - o[0], -SQ2 * p.y - o[1],
                                         -SQ2 * p.z - o[2], -SQ2 * p.w - o[3]);
                long base4 = (ch < 64)
                    ? (1L * (SEG / 4) + ((long)((b << 6) + ch)      << 12))
                    : (4L * (SEG / 4) + ((long)((b << 6) + ch - 64) << 12));
                ((float4*)out)[base4 + (i << 5) + jb] = res;
            }
        }
    }
}

extern "C" void kernel_launch(void* const* d_in, const int* in_sizes, int n_in,
                              void* d_out, int out_size) {
    const float* x = (const float*)d_in[0];
    float* out = (float*)d_out;
    (void)in_sizes; (void)n_in; (void)out_size;

    const int T = 256;
    k_AB<<<1024, T>>>(x, out);        // c -> seg0
    k_C<<<2048, T>>>(out, x);         // d -> bB
    k_qp1<<<8192, T>>>();             // p0|p1 -> bP
    k_D<6, 0><<<1024, T>>>();         // y0a -> bA[0..HM)
    k_D<5, 1><<<1024, T>>>();         // y1a -> bA[HM..)
    k_qp2<<<8192, T>>>();             // p0b|p1b -> bP
    k_E<6, 0><<<1024, T>>>(out);      // e0 -> segs2/3
    k_E<5, 1><<<1024, T>>>(out);      // e1 -> segs1/4
}

// round 13
// speedup vs baseline: 6.5897x; 1.1565x over previous
#include <cuda_runtime.h>

// ------- scratch: 3 x 64MB = 192MB; referenced ONLY from device code ------
static __device__ float bA[16777216];   // z0 | z1 (stage D outputs)
static __device__ float bB[16777216];   // d (stage C/D)
static __device__ float bP[16777216];   // p0|p1 (stage D), then p0b|p1b (stage E)

// ---------------- filters ------------------------------------------------
__constant__ float c_h[9] = {
     0.037828455506995f, -0.02384946501938f, -0.11062440441842f,
     0.37740285561265f,   0.8526986790094f,   0.37740285561265f,
    -0.11062440441842f,  -0.02384946501938f,  0.037828455506995f };
__constant__ float c_g[7] = {
    -0.064538882628938f, -0.040689417609558f, 0.41809227322221f,
     0.78848561640566f,   0.41809227322221f, -0.040689417609558f,
    -0.064538882628938f };
__constant__ float c_f[12] = {
     0.0144f,  0.0272f,  0.0526f,  0.0972f,  0.193f,  0.63f,
    -0.63f,   -0.193f,  -0.0972f, -0.0526f, -0.0272f, -0.0144f };

#define INV_SQ2 0.7071067811865476f
#define SQ2     1.4142135623730951f
#define SEG     4194304L
#define HM 8388608

__device__ __forceinline__ float4 f4fma(float c, float4 v, float4 a) {
    a.x = fmaf(c, v.x, a.x); a.y = fmaf(c, v.y, a.y);
    a.z = fmaf(c, v.z, a.z); a.w = fmaf(c, v.w, a.w);
    return a;
}
__device__ __forceinline__ float2 f2fma(float c, float2 v, float2 a) {
    a.x = fmaf(c, v.x, a.x); a.y = fmaf(c, v.y, a.y);
    return a;
}

// ===== K_AB: fused vh(stride2) + hh(stride2). x -> out seg0 (c) ===========
__global__ void __launch_bounds__(256) k_AB(const float* __restrict__ x,
                                            float* __restrict__ outc) {
    __shared__ float4 t[2048];          // 32 rows x 64 f4
    int rb = blockIdx.x & 3, img = blockIdx.x >> 2;
    int tid = threadIdx.x;
    const float4* xi = (const float4*)x + ((long)img << 14);
    {
        int jb = tid & 63, ib = tid >> 6;
        for (int rr = ib; rr < 32; rr += 4) {
            int i2 = rb * 32 + rr;
            float4 s = {0.f, 0.f, 0.f, 0.f};
#pragma unroll
            for (int k = 0; k < 9; ++k)
                s = f4fma(c_h[k], xi[(((2 * i2 + k - 4) & 255) << 6) + jb], s);
            t[rr * 64 + jb] = s;
        }
    }
    __syncthreads();
    {
        int jb = tid & 31, ib = tid >> 5;
        for (int rr = ib; rr < 32; rr += 8) {
            const float4* trow = t + rr * 64;
            float r[20];
#pragma unroll
            for (int s = 0; s < 5; ++s) {
                float4 v = trow[(2 * jb - 2 + s + 64) & 63];
                r[4*s] = v.x; r[4*s+1] = v.y; r[4*s+2] = v.z; r[4*s+3] = v.w;
            }
            float o[4];
#pragma unroll
            for (int m = 0; m < 4; ++m) {
                float s = 0.f;
#pragma unroll
                for (int k = 0; k < 9; ++k)
                    s = fmaf(c_h[k], r[2 * m + k + 4], s);
                o[m] = s;
            }
            int i = rb * 32 + rr;
            ((float4*)outc)[((long)img << 12) + (i << 5) + jb] =
                make_float4(o[0], o[1], o[2], o[3]);
        }
    }
}

// ===== K_C: fused (upsample+vert g) + (horiz g + sub). c,x -> bB = d ======
__global__ void __launch_bounds__(256) k_C(const float* __restrict__ cc,
                                           const float* __restrict__ x) {
    __shared__ float v[4096];           // 32 rows x 128 evencols
    int rb = blockIdx.x & 7, img = blockIdx.x >> 3;
    int tid = threadIdx.x;
    const float4* ci = (const float4*)cc + ((long)img << 12);
    {
        int jb = tid & 31, ib = tid >> 5;
        for (int rr = ib; rr < 32; rr += 8) {
            int i = rb * 32 + rr;
            float4 s = {0.f, 0.f, 0.f, 0.f};
            if (i & 1) {
#pragma unroll
                for (int k = 0; k < 7; k += 2)
                    s = f4fma(c_g[k], ci[((((i + k - 3) & 255) >> 1) << 5) + jb], s);
            } else {
#pragma unroll
                for (int k = 1; k < 7; k += 2)
                    s = f4fma(c_g[k], ci[((((i + k - 3) & 255) >> 1) << 5) + jb], s);
            }
            ((float4*)v)[rr * 32 + jb] = s;
        }
    }
    __syncthreads();
    {
        int jb = tid & 63, ib = tid >> 6;
        for (int rr = ib; rr < 32; rr += 4) {
            int i = rb * 32 + rr;
            const float* vr = v + rr * 128;
            float o[4];
#pragma unroll
            for (int m = 0; m < 4; ++m) {
                int j = 4 * jb + m;
                float s = 0.f;
                if (m & 1) {
#pragma unroll
                    for (int k = 0; k < 7; k += 2)
                        s = fmaf(c_g[k], vr[((j + k - 3) & 255) >> 1], s);
                } else {
#pragma unroll
                    for (int k = 1; k < 7; k += 2)
                        s = fmaf(c_g[k], vr[((j + k - 3) & 255) >> 1], s);
                }
                o[m] = s;
            }
            long fi = ((long)img << 14) + (i << 6) + jb;
            float4 xv = ((const float4*)x)[fi];
            ((float4*)bB)[fi] =
                make_float4(xv.x - o[0], xv.y - o[1], xv.z - o[2], xv.w - o[3]);
        }
    }
}

// ===== K_qp1: stage-D quincunx via diamond smem tile. bB(d) -> bP =========
// p0[i,j]=d[(i-j)%256,(i+j)%256]; p1 same row, col+1. 32x32 output tiles.
__global__ void __launch_bounds__(256) k_qp1() {
    __shared__ __align__(16) float sm[64 * 68];   // 64 rows x 68-pitch
    int img = blockIdx.x >> 5;
    int tl = blockIdx.x & 31;
    int i0 = (tl >> 3) << 5, j0 = (tl & 7) << 5;
    int tid = threadIdx.x;
    const float4* di = (const float4*)bB + ((long)img << 14);
    int c0f = ((i0 + j0) & 255) >> 2;
    int rbase = i0 - j0 - 31;
#pragma unroll
    for (int r = 0; r < 4; ++r) {
        int p = tid + 256 * r;                  // 0..1023
        int u = p >> 4, vb = p & 15;
        int ru = (rbase + u) & 255;
        float4 val = di[(ru << 6) + ((c0f + vb) & 63)];
        *(float4*)&sm[u * 68 + 4 * vb] = val;
    }
    __syncthreads();
    int li = tid >> 3, lj0 = (tid & 7) << 2;
    float a[4], b[4];
#pragma unroll
    for (int m = 0; m < 4; ++m) {
        int lj = lj0 + m;
        int u = 31 + li - lj, vv = li + lj;
        a[m] = sm[u * 68 + vv];
        b[m] = sm[u * 68 + vv + 1];
    }
    long fi = ((long)img << 13) + ((i0 + li) << 6) + (j0 >> 2) + (tid & 7);
    ((float4*)bP)[fi]        = make_float4(a[0], a[1], a[2], a[3]);
    ((float4*)(bP + HM))[fi] = make_float4(b[0], b[1], b[2], b[3]);
}

// ===== K_D: float2 sliding-window qper_col vert f + horiz f + combine.
//  (128,256) images, 16-row tiles. grid = 256 img x 8 rowblocks.
//  OFF=6 (SRC=0): vert p1(bP+HM), comb p0(bP)    -> z0 (bA[0..HM))
//  OFF=5 (SRC=1): vert z0(bA),    comb p1(bP+HM) -> z1 (bA[HM..)) =========
template<int OFF, int SRC>
__global__ void __launch_bounds__(256) k_D() {
    __shared__ __align__(16) float t[16 * 256];   // 16 rows x 256 floats
    int rb = blockIdx.x & 7, img = blockIdx.x >> 3;
    int tid = threadIdx.x;
    const float2* s2 = (const float2*)(
        (SRC ? (const float4*)bA : (const float4*)(bP + HM)) + ((long)img << 13));
    // phase 1: vertical 12-tap f, 8 consecutive rows per thread, float2 cols
    {
        int j2 = tid & 127, strip = tid >> 7;
        int r0 = rb * 16 + strip * 8;
        float2 acc[8];
#pragma unroll
        for (int q = 0; q < 8; ++q) acc[q] = make_float2(0.f, 0.f);
#pragma unroll
        for (int s = 0; s < 19; ++s) {
            int a = r0 - OFF + s;
            int row = a, c2 = j2;
            if (a < 0)        { row = a + 128; c2 = (j2 + 64) & 127; }
            else if (a > 127) { row = a - 128; c2 = (j2 + 64) & 127; }
            float2 v = s2[(row << 7) + c2];
#pragma unroll
            for (int q = 0; q < 8; ++q) {
                int k = s - q;
                if (k >= 0 && k < 12) acc[q] = f2fma(c_f[k], v, acc[q]);
            }
        }
#pragma unroll
        for (int q = 0; q < 8; ++q)
            ((float2*)t)[(strip * 8 + q) * 128 + j2] = acc[q];
    }
    __syncthreads();
    // phase 2: horizontal f + combine
    {
        int jb = tid & 63, ib = tid >> 6;
        for (int rr = ib; rr < 16; rr += 4) {
            const float4* trow = (const float4*)t + rr * 64;
            float r[20];
#pragma unroll
            for (int s = 0; s < 5; ++s) {
                float4 v = trow[(jb - 2 + s + 64) & 63];
                r[4*s] = v.x; r[4*s+1] = v.y; r[4*s+2] = v.z; r[4*s+3] = v.w;
            }
            float o[4];
#pragma unroll
            for (int m = 0; m < 4; ++m) {
                float s = 0.f;
#pragma unroll
                for (int k = 0; k < 12; ++k)
                    s = fmaf(c_f[k], r[m + k + 8 - OFF], s);
                o[m] = s;
            }
            int i = rb * 16 + rr;
            long fi = ((long)img << 13) + (i << 6) + jb;
            if (OFF == 6) {
                float4 p = ((const float4*)bP)[fi];
                ((float4*)bA)[fi] = make_float4((p.x - o[0]) * INV_SQ2,
                                                (p.y - o[1]) * INV_SQ2,
                                                (p.z - o[2]) * INV_SQ2,
                                                (p.w - o[3]) * INV_SQ2);
            } else {
                float4 p = ((const float4*)(bP + HM))[fi];
                ((float4*)(bA + HM))[fi] = make_float4(-SQ2 * p.x - o[0],
                                                       -SQ2 * p.y - o[1],
                                                       -SQ2 * p.z - o[2],
                                                       -SQ2 * p.w - o[3]);
            }
        }
    }
}

// ===== K_qp2: stage-E quincunx via diamond smem tile. bA(z) -> bP ========
// p0b[i,j]=z[(i+j)%128,(j-i+128*wrap)%256]; wrap const per diagonal s=i+j.
__global__ void __launch_bounds__(256) k_qp2() {
    __shared__ __align__(16) float sm[64 * 68];
    int img = blockIdx.x >> 4;                 // 512 imgs
    int tl = blockIdx.x & 15;
    int i0 = (tl >> 2) << 5, j0 = (tl & 3) << 5;
    int b = img >> 7, ch = img & 127;
    const float4* zi = (ch < 64)
        ? ((const float4*)bA        + ((long)((b << 6) + ch)      << 13))
        : ((const float4*)(bA + HM) + ((long)((b << 6) + ch - 64) << 13));
    int tid = threadIdx.x;
#pragma unroll
    for (int r = 0; r < 4; ++r) {
        int p = tid + 256 * r;
        int s = p >> 4, vb = p & 15;
        int aa = i0 + j0 + s;                  // < 256 always
        int row = aa & 127;
        int w = aa >> 7;
        int start = (j0 - i0 - 32 + (w << 7)) & 255;   // multiple of 4
        float4 val = zi[(row << 6) + (((start >> 2) + vb) & 63)];
        *(float4*)&sm[s * 68 + 4 * vb] = val;
    }
    __syncthreads();
    int li = tid >> 3, lj0 = (tid & 7) << 2;
    float a[4], bb[4];
#pragma unroll
    for (int m = 0; m < 4; ++m) {
        int lj = lj0 + m;
        int s = li + lj, vv = lj - li + 32;
        a[m]  = sm[s * 68 + vv];
        bb[m] = sm[(s + 1) * 68 + vv];
    }
    long fi = ((long)img << 12) + ((i0 + li) << 5) + (j0 >> 2) + (tid & 7);
    ((float4*)bP)[fi]        = make_float4(a[0], a[1], a[2], a[3]);
    ((float4*)(bP + HM))[fi] = make_float4(bb[0], bb[1], bb[2], bb[3]);
}

// ===== K_E: float2 sliding-window periodic vert f + horiz f + combine.
//  (128,128) images, 32-row tiles. grid = 512 img x 4 rowblocks.
//  OFF=6 (SRC=0): vert p1b(bP+HM), comb p0b(bP) -> out segs2/3
//  OFF=5 (SRC=1): vert e0 (from out), comb p1b  -> out segs1/4 ============
template<int OFF, int SRC>
__global__ void __launch_bounds__(256) k_E(float* __restrict__ out) {
    __shared__ __align__(16) float t[32 * 128];   // 32 rows x 128 floats
    int rb = blockIdx.x & 3, img = blockIdx.x >> 2;
    int tid = threadIdx.x;
    int b = img >> 7, ch = img & 127;
    const float2* s2;
    if (SRC) {
        long base4 = (ch < 64)
            ? (2L * (SEG / 4) + ((long)((b << 6) + ch)      << 12))
            : (3L * (SEG / 4) + ((long)((b << 6) + ch - 64) << 12));
        s2 = (const float2*)((const float4*)out + base4);
    } else {
        s2 = (const float2*)((const float4*)(bP + HM) + ((long)img << 12));
    }
    // phase 1
    {
        int j2 = tid & 63, strip = tid >> 6;
        int r0 = rb * 32 + strip * 8;
        float2 acc[8];
#pragma unroll
        for (int q = 0; q < 8; ++q) acc[q] = make_float2(0.f, 0.f);
#pragma unroll
        for (int s = 0; s < 19; ++s) {
            int row = (r0 - OFF + s + 128) & 127;
            float2 v = s2[(row << 6) + j2];
#pragma unroll
            for (int q = 0; q < 8; ++q) {
                int k = s - q;
                if (k >= 0 && k < 12) acc[q] = f2fma(c_f[k], v, acc[q]);
            }
        }
#pragma unroll
        for (int q = 0; q < 8; ++q)
            ((float2*)t)[(strip * 8 + q) * 64 + j2] = acc[q];
    }
    __syncthreads();
    // phase 2
    {
        int jb = tid & 31, ib = tid >> 5;
        for (int rr = ib; rr < 32; rr += 8) {
            const float4* trow = (const float4*)t + rr * 32;
            float r[20];
#pragma unroll
            for (int s = 0; s < 5; ++s) {
                float4 v = trow[(jb - 2 + s + 32) & 31];
                r[4*s] = v.x; r[4*s+1] = v.y; r[4*s+2] = v.z; r[4*s+3] = v.w;
            }
            float o[4];
#pragma unroll
            for (int m = 0; m < 4; ++m) {
                float s = 0.f;
#pragma unroll
                for (int k = 0; k < 12; ++k)
                    s = fmaf(c_f[k], r[m + k + 8 - OFF], s);
                o[m] = s;
            }
            int i = rb * 32 + rr;
            long fi = ((long)img << 12) + (i << 5) + jb;
            if (OFF == 6) {
                float4 p = ((const float4*)bP)[fi];
                float4 res = make_float4((p.x - o[0]) * INV_SQ2,
                                         (p.y - o[1]) * INV_SQ2,
                                         (p.z - o[2]) * INV_SQ2,
                                         (p.w - o[3]) * INV_SQ2);
                long base4 = (ch < 64)
                    ? (2L * (SEG / 4) + ((long)((b << 6) + ch)      << 12))
                    : (3L * (SEG / 4) + ((long)((b << 6) + ch - 64) << 12));
                ((float4*)out)[base4 + (i << 5) + jb] = res;
            } else {
                float4 p = ((const float4*)(bP + HM))[fi];
                float4 res = make_float4(-SQ2 * p.x - o[0], -SQ2 * p.y - o[1],
                                         -SQ2 * p.z - o[2], -SQ2 * p.w - o[3]);
                long base4 = (ch < 64)
                    ? (1L * (SEG / 4) + ((long)((b << 6) + ch)      << 12))
                    : (4L * (SEG / 4) + ((long)((b << 6) + ch - 64) << 12));
                ((float4*)out)[base4 + (i << 5) + jb] = res;
            }
        }
    }
}

extern "C" void kernel_launch(void* const* d_in, const int* in_sizes, int n_in,
                              void* d_out, int out_size) {
    const float* x = (const float*)d_in[0];
    float* out = (float*)d_out;
    (void)in_sizes; (void)n_in; (void)out_size;

    const int T = 256;
    k_AB<<<1024, T>>>(x, out);        // c -> seg0
    k_C<<<2048, T>>>(out, x);         // d -> bB
    k_qp1<<<8192, T>>>();             // p0|p1 -> bP
    k_D<6, 0><<<2048, T>>>();         // y0a -> bA[0..HM)
    k_D<5, 1><<<2048, T>>>();         // y1a -> bA[HM..)
    k_qp2<<<8192, T>>>();             // p0b|p1b -> bP
    k_E<6, 0><<<2048, T>>>(out);      // e0 -> segs2/3
    k_E<5, 1><<<2048, T>>>(out);      // e1 -> segs1/4
}

// round 14
// speedup vs baseline: 6.7508x; 1.0244x over previous
#include <cuda_runtime.h>

// ------- scratch: 3 x 64MB = 192MB; referenced ONLY from device code ------
static __device__ float bA[16777216];   // z0 | z1 (stage D outputs)
static __device__ float bB[16777216];   // d (stage C/D)
static __device__ float bP[16777216];   // p0|p1 (stage D), then p0b|p1b (stage E)

// ---------------- filters (scalar + packed-pair tables) -------------------
__constant__ float c_h[9] = {
     0.037828455506995f, -0.02384946501938f, -0.11062440441842f,
     0.37740285561265f,   0.8526986790094f,   0.37740285561265f,
    -0.11062440441842f,  -0.02384946501938f,  0.037828455506995f };
__constant__ float c_g[7] = {
    -0.064538882628938f, -0.040689417609558f, 0.41809227322221f,
     0.78848561640566f,   0.41809227322221f, -0.040689417609558f,
    -0.064538882628938f };
__constant__ float c_f[12] = {
     0.0144f,  0.0272f,  0.0526f,  0.0972f,  0.193f,  0.63f,
    -0.63f,   -0.193f,  -0.0972f, -0.0526f, -0.0272f, -0.0144f };
__constant__ float2 c_h2[9] = {
    {0.037828455506995f,0.037828455506995f}, {-0.02384946501938f,-0.02384946501938f},
    {-0.11062440441842f,-0.11062440441842f}, {0.37740285561265f,0.37740285561265f},
    {0.8526986790094f,0.8526986790094f},     {0.37740285561265f,0.37740285561265f},
    {-0.11062440441842f,-0.11062440441842f}, {-0.02384946501938f,-0.02384946501938f},
    {0.037828455506995f,0.037828455506995f} };
__constant__ float2 c_g2[7] = {
    {-0.064538882628938f,-0.064538882628938f}, {-0.040689417609558f,-0.040689417609558f},
    {0.41809227322221f,0.41809227322221f},     {0.78848561640566f,0.78848561640566f},
    {0.41809227322221f,0.41809227322221f},     {-0.040689417609558f,-0.040689417609558f},
    {-0.064538882628938f,-0.064538882628938f} };
__constant__ float2 c_f2[12] = {
    {0.0144f,0.0144f},  {0.0272f,0.0272f},  {0.0526f,0.0526f},  {0.0972f,0.0972f},
    {0.193f,0.193f},    {0.63f,0.63f},      {-0.63f,-0.63f},    {-0.193f,-0.193f},
    {-0.0972f,-0.0972f},{-0.0526f,-0.0526f},{-0.0272f,-0.0272f},{-0.0144f,-0.0144f} };

#define INV_SQ2 0.7071067811865476f
#define SQ2     1.4142135623730951f
#define SEG     4194304L
#define HM 8388608

// packed dual-FMA: two independent IEEE rn fmas -> bit-identical to fmaf x2
__device__ __forceinline__ float2 f2fmap(float2 c, float2 v, float2 a) {
    unsigned long long au = *(unsigned long long*)&a;
    unsigned long long cu = *(unsigned long long*)&c;
    unsigned long long vu = *(unsigned long long*)&v;
    asm("fma.rn.f32x2 %0, %1, %2, %0;" : "+l"(au) : "l"(cu), "l"(vu));
    float2 r; *(unsigned long long*)&r = au; return r;
}
__device__ __forceinline__ float4 f4fmap(float2 c, float4 v, float4 a) {
    float2 lo = f2fmap(c, make_float2(v.x, v.y), make_float2(a.x, a.y));
    float2 hi = f2fmap(c, make_float2(v.z, v.w), make_float2(a.z, a.w));
    return make_float4(lo.x, lo.y, hi.x, hi.y);
}

// ===== K_AB: fused vh(stride2) + hh(stride2). x -> out seg0 (c) ===========
__global__ void __launch_bounds__(256) k_AB(const float* __restrict__ x,
                                            float* __restrict__ outc) {
    __shared__ float4 t[2048];          // 32 rows x 64 f4
    int rb = blockIdx.x & 3, img = blockIdx.x >> 2;
    int tid = threadIdx.x;
    const float4* xi = (const float4*)x + ((long)img << 14);
    {
        int jb = tid & 63, ib = tid >> 6;
        for (int rr = ib; rr < 32; rr += 4) {
            int i2 = rb * 32 + rr;
            float4 s = {0.f, 0.f, 0.f, 0.f};
#pragma unroll
            for (int k = 0; k < 9; ++k)
                s = f4fmap(c_h2[k], xi[(((2 * i2 + k - 4) & 255) << 6) + jb], s);
            t[rr * 64 + jb] = s;
        }
    }
    __syncthreads();
    {
        int jb = tid & 31, ib = tid >> 5;
        for (int rr = ib; rr < 32; rr += 8) {
            const float4* trow = t + rr * 64;
            float r[20];
#pragma unroll
            for (int s = 0; s < 5; ++s) {
                float4 v = trow[(2 * jb - 2 + s + 64) & 63];
                r[4*s] = v.x; r[4*s+1] = v.y; r[4*s+2] = v.z; r[4*s+3] = v.w;
            }
            float o[4];
#pragma unroll
            for (int m = 0; m < 4; ++m) {
                float s = 0.f;
#pragma unroll
                for (int k = 0; k < 9; ++k)
                    s = fmaf(c_h[k], r[2 * m + k + 4], s);
                o[m] = s;
            }
            int i = rb * 32 + rr;
            ((float4*)outc)[((long)img << 12) + (i << 5) + jb] =
                make_float4(o[0], o[1], o[2], o[3]);
        }
    }
}

// ===== K_C: fused (upsample+vert g) + (horiz g + sub). c,x -> bB = d ======
__global__ void __launch_bounds__(256) k_C(const float* __restrict__ cc,
                                           const float* __restrict__ x) {
    __shared__ float v[4096];           // 32 rows x 128 evencols
    int rb = blockIdx.x & 7, img = blockIdx.x >> 3;
    int tid = threadIdx.x;
    const float4* ci = (const float4*)cc + ((long)img << 12);
    {
        int jb = tid & 31, ib = tid >> 5;
        for (int rr = ib; rr < 32; rr += 8) {
            int i = rb * 32 + rr;
            float4 s = {0.f, 0.f, 0.f, 0.f};
            if (i & 1) {
#pragma unroll
                for (int k = 0; k < 7; k += 2)
                    s = f4fmap(c_g2[k], ci[((((i + k - 3) & 255) >> 1) << 5) + jb], s);
            } else {
#pragma unroll
                for (int k = 1; k < 7; k += 2)
                    s = f4fmap(c_g2[k], ci[((((i + k - 3) & 255) >> 1) << 5) + jb], s);
            }
            ((float4*)v)[rr * 32 + jb] = s;
        }
    }
    __syncthreads();
    {
        int jb = tid & 63, ib = tid >> 6;
        for (int rr = ib; rr < 32; rr += 4) {
            int i = rb * 32 + rr;
            const float* vr = v + rr * 128;
            float o[4];
#pragma unroll
            for (int m = 0; m < 4; ++m) {
                int j = 4 * jb + m;
                float s = 0.f;
                if (m & 1) {
#pragma unroll
                    for (int k = 0; k < 7; k += 2)
                        s = fmaf(c_g[k], vr[((j + k - 3) & 255) >> 1], s);
                } else {
#pragma unroll
                    for (int k = 1; k < 7; k += 2)
                        s = fmaf(c_g[k], vr[((j + k - 3) & 255) >> 1], s);
                }
                o[m] = s;
            }
            long fi = ((long)img << 14) + (i << 6) + jb;
            float4 xv = ((const float4*)x)[fi];
            ((float4*)bB)[fi] =
                make_float4(xv.x - o[0], xv.y - o[1], xv.z - o[2], xv.w - o[3]);
        }
    }
}

// ===== K_qp1: stage-D quincunx via diamond smem tile. bB(d) -> bP =========
__global__ void __launch_bounds__(256) k_qp1() {
    __shared__ __align__(16) float sm[64 * 68];   // 64 rows x 68-pitch
    int img = blockIdx.x >> 5;
    int tl = blockIdx.x & 31;
    int i0 = (tl >> 3) << 5, j0 = (tl & 7) << 5;
    int tid = threadIdx.x;
    const float4* di = (const float4*)bB + ((long)img << 14);
    int c0f = ((i0 + j0) & 255) >> 2;
    int rbase = i0 - j0 - 31;
#pragma unroll
    for (int r = 0; r < 4; ++r) {
        int p = tid + 256 * r;                  // 0..1023
        int u = p >> 4, vb = p & 15;
        int ru = (rbase + u) & 255;
        float4 val = di[(ru << 6) + ((c0f + vb) & 63)];
        *(float4*)&sm[u * 68 + 4 * vb] = val;
    }
    __syncthreads();
    int li = tid >> 3, lj0 = (tid & 7) << 2;
    float a[4], b[4];
#pragma unroll
    for (int m = 0; m < 4; ++m) {
        int lj = lj0 + m;
        int u = 31 + li - lj, vv = li + lj;
        a[m] = sm[u * 68 + vv];
        b[m] = sm[u * 68 + vv + 1];
    }
    long fi = ((long)img << 13) + ((i0 + li) << 6) + (j0 >> 2) + (tid & 7);
    ((float4*)bP)[fi]        = make_float4(a[0], a[1], a[2], a[3]);
    ((float4*)(bP + HM))[fi] = make_float4(b[0], b[1], b[2], b[3]);
}

// ===== K_D: packed-fma sliding-window qper_col vert f + horiz f + combine.
//  (128,256) images, 16-row tiles. grid = 256 img x 8 rowblocks. ===========
template<int OFF, int SRC>
__global__ void __launch_bounds__(256) k_D() {
    __shared__ __align__(16) float t[16 * 256];   // 16 rows x 256 floats
    int rb = blockIdx.x & 7, img = blockIdx.x >> 3;
    int tid = threadIdx.x;
    const float2* s2 = (const float2*)(
        (SRC ? (const float4*)bA : (const float4*)(bP + HM)) + ((long)img << 13));
    // phase 1: vertical 12-tap f, 8 consecutive rows per thread, packed fma
    {
        int j2 = tid & 127, strip = tid >> 7;
        int r0 = rb * 16 + strip * 8;
        float2 acc[8];
#pragma unroll
        for (int q = 0; q < 8; ++q) acc[q] = make_float2(0.f, 0.f);
#pragma unroll
        for (int s = 0; s < 19; ++s) {
            int a = r0 - OFF + s;
            int row = a, c2 = j2;
            if (a < 0)        { row = a + 128; c2 = (j2 + 64) & 127; }
            else if (a > 127) { row = a - 128; c2 = (j2 + 64) & 127; }
            float2 v = s2[(row << 7) + c2];
#pragma unroll
            for (int q = 0; q < 8; ++q) {
                int k = s - q;
                if (k >= 0 && k < 12) acc[q] = f2fmap(c_f2[k], v, acc[q]);
            }
        }
#pragma unroll
        for (int q = 0; q < 8; ++q)
            ((float2*)t)[(strip * 8 + q) * 128 + j2] = acc[q];
    }
    __syncthreads();
    // phase 2: horizontal f + combine
    {
        int jb = tid & 63, ib = tid >> 6;
        for (int rr = ib; rr < 16; rr += 4) {
            const float4* trow = (const float4*)t + rr * 64;
            float r[20];
#pragma unroll
            for (int s = 0; s < 5; ++s) {
                float4 v = trow[(jb - 2 + s + 64) & 63];
                r[4*s] = v.x; r[4*s+1] = v.y; r[4*s+2] = v.z; r[4*s+3] = v.w;
            }
            float o[4];
#pragma unroll
            for (int m = 0; m < 4; ++m) {
                float s = 0.f;
#pragma unroll
                for (int k = 0; k < 12; ++k)
                    s = fmaf(c_f[k], r[m + k + 8 - OFF], s);
                o[m] = s;
            }
            int i = rb * 16 + rr;
            long fi = ((long)img << 13) + (i << 6) + jb;
            if (OFF == 6) {
                float4 p = ((const float4*)bP)[fi];
                ((float4*)bA)[fi] = make_float4((p.x - o[0]) * INV_SQ2,
                                                (p.y - o[1]) * INV_SQ2,
                                                (p.z - o[2]) * INV_SQ2,
                                                (p.w - o[3]) * INV_SQ2);
            } else {
                float4 p = ((const float4*)(bP + HM))[fi];
                ((float4*)(bA + HM))[fi] = make_float4(-SQ2 * p.x - o[0],
                                                       -SQ2 * p.y - o[1],
                                                       -SQ2 * p.z - o[2],
                                                       -SQ2 * p.w - o[3]);
            }
        }
    }
}

// ===== K_qp2: stage-E quincunx via diamond smem tile. bA(z) -> bP ========
__global__ void __launch_bounds__(256) k_qp2() {
    __shared__ __align__(16) float sm[64 * 68];
    int img = blockIdx.x >> 4;                 // 512 imgs
    int tl = blockIdx.x & 15;
    int i0 = (tl >> 2) << 5, j0 = (tl & 3) << 5;
    int b = img >> 7, ch = img & 127;
    const float4* zi = (ch < 64)
        ? ((const float4*)bA        + ((long)((b << 6) + ch)      << 13))
        : ((const float4*)(bA + HM) + ((long)((b << 6) + ch - 64) << 13));
    int tid = threadIdx.x;
#pragma unroll
    for (int r = 0; r < 4; ++r) {
        int p = tid + 256 * r;
        int s = p >> 4, vb = p & 15;
        int aa = i0 + j0 + s;                  // < 256 always
        int row = aa & 127;
        int w = aa >> 7;
        int start = (j0 - i0 - 32 + (w << 7)) & 255;   // multiple of 4
        float4 val = zi[(row << 6) + (((start >> 2) + vb) & 63)];
        *(float4*)&sm[s * 68 + 4 * vb] = val;
    }
    __syncthreads();
    int li = tid >> 3, lj0 = (tid & 7) << 2;
    float a[4], bb[4];
#pragma unroll
    for (int m = 0; m < 4; ++m) {
        int lj = lj0 + m;
        int s = li + lj, vv = lj - li + 32;
        a[m]  = sm[s * 68 + vv];
        bb[m] = sm[(s + 1) * 68 + vv];
    }
    long fi = ((long)img << 12) + ((i0 + li) << 5) + (j0 >> 2) + (tid & 7);
    ((float4*)bP)[fi]        = make_float4(a[0], a[1], a[2], a[3]);
    ((float4*)(bP + HM))[fi] = make_float4(bb[0], bb[1], bb[2], bb[3]);
}

// ===== K_E: packed-fma sliding-window periodic vert f + horiz f + combine.
//  (128,128) images, 32-row tiles. grid = 512 img x 4 rowblocks. ===========
template<int OFF, int SRC>
__global__ void __launch_bounds__(256) k_E(float* __restrict__ out) {
    __shared__ __align__(16) float t[32 * 128];   // 32 rows x 128 floats
    int rb = blockIdx.x & 3, img = blockIdx.x >> 2;
    int tid = threadIdx.x;
    int b = img >> 7, ch = img & 127;
    const float2* s2;
    if (SRC) {
        long base4 = (ch < 64)
            ? (2L * (SEG / 4) + ((long)((b << 6) + ch)      << 12))
            : (3L * (SEG / 4) + ((long)((b << 6) + ch - 64) << 12));
        s2 = (const float2*)((const float4*)out + base4);
    } else {
        s2 = (const float2*)((const float4*)(bP + HM) + ((long)img << 12));
    }
    // phase 1
    {
        int j2 = tid & 63, strip = tid >> 6;
        int r0 = rb * 32 + strip * 8;
        float2 acc[8];
#pragma unroll
        for (int q = 0; q < 8; ++q) acc[q] = make_float2(0.f, 0.f);
#pragma unroll
        for (int s = 0; s < 19; ++s) {
            int row = (r0 - OFF + s + 128) & 127;
            float2 v = s2[(row << 6) + j2];
#pragma unroll
            for (int q = 0; q < 8; ++q) {
                int k = s - q;
                if (k >= 0 && k < 12) acc[q] = f2fmap(c_f2[k], v, acc[q]);
            }
        }
#pragma unroll
        for (int q = 0; q < 8; ++q)
            ((float2*)t)[(strip * 8 + q) * 64 + j2] = acc[q];
    }
    __syncthreads();
    // phase 2
    {
        int jb = tid & 31, ib = tid >> 5;
        for (int rr = ib; rr < 32; rr += 8) {
            const float4* trow = (const float4*)t + rr * 32;
            float r[20];
#pragma unroll
            for (int s = 0; s < 5; ++s) {
                float4 v = trow[(jb - 2 + s + 32) & 31];
                r[4*s] = v.x; r[4*s+1] = v.y; r[4*s+2] = v.z; r[4*s+3] = v.w;
            }
            float o[4];
#pragma unroll
            for (int m = 0; m < 4; ++m) {
                float s = 0.f;
#pragma unroll
                for (int k = 0; k < 12; ++k)
                    s = fmaf(c_f[k], r[m + k + 8 - OFF], s);
                o[m] = s;
            }
            int i = rb * 32 + rr;
            long fi = ((long)img << 12) + (i << 5) + jb;
            if (OFF == 6) {
                float4 p = ((const float4*)bP)[fi];
                float4 res = make_float4((p.x - o[0]) * INV_SQ2,
                                         (p.y - o[1]) * INV_SQ2,
                                         (p.z - o[2]) * INV_SQ2,
                                         (p.w - o[3]) * INV_SQ2);
                long base4 = (ch < 64)
                    ? (2L * (SEG / 4) + ((long)((b << 6) + ch)      << 12))
                    : (3L * (SEG / 4) + ((long)((b << 6) + ch - 64) << 12));
                ((float4*)out)[base4 + (i << 5) + jb] = res;
            } else {
                float4 p = ((const float4*)(bP + HM))[fi];
                float4 res = make_float4(-SQ2 * p.x - o[0], -SQ2 * p.y - o[1],
                                         -SQ2 * p.z - o[2], -SQ2 * p.w - o[3]);
                long base4 = (ch < 64)
                    ? (1L * (SEG / 4) + ((long)((b << 6) + ch)      << 12))
                    : (4L * (SEG / 4) + ((long)((b << 6) + ch - 64) << 12));
                ((float4*)out)[base4 + (i << 5) + jb] = res;
            }
        }
    }
}

extern "C" void kernel_launch(void* const* d_in, const int* in_sizes, int n_in,
                              void* d_out, int out_size) {
    const float* x = (const float*)d_in[0];
    float* out = (float*)d_out;
    (void)in_sizes; (void)n_in; (void)out_size;

    const int T = 256;
    k_AB<<<1024, T>>>(x, out);        // c -> seg0
    k_C<<<2048, T>>>(out, x);         // d -> bB
    k_qp1<<<8192, T>>>();             // p0|p1 -> bP
    k_D<6, 0><<<2048, T>>>();         // y0a -> bA[0..HM)
    k_D<5, 1><<<2048, T>>>();         // y1a -> bA[HM..)
    k_qp2<<<8192, T>>>();             // p0b|p1b -> bP
    k_E<6, 0><<<2048, T>>>(out);      // e0 -> segs2/3
    k_E<5, 1><<<2048, T>>>(out);      // e1 -> segs1/4
}